// round 8
// baseline (speedup 1.0000x reference)
#include <cuda_runtime.h>
#include <cuda_bf16.h>
#include <stdint.h>
#include <math.h>

// ============================================================================
// Scratch (device globals — no allocations allowed).
// ============================================================================
__device__ float g_ctx[48ull * 8192ull * 64ull];   // [e][row][h], ~100.7 MB
// Pre-split bf16 operands (hi = bf16(x), lo = bf16(x - hi)).
__device__ __align__(16) __nv_bfloat16 g_xhi [8192ull * 1024];      // x
__device__ __align__(16) __nv_bfloat16 g_xlo [8192ull * 1024];
__device__ __align__(16) __nv_bfloat16 g_wthi[48ull * 64 * 1024];   // Wqkv^T [e][h][d]
__device__ __align__(16) __nv_bfloat16 g_wtlo[48ull * 64 * 1024];
__device__ __align__(16) __nv_bfloat16 g_wphi[1024ull * 1024];      // Wp [n][k]
__device__ __align__(16) __nv_bfloat16 g_wplo[1024ull * 1024];
__device__ __align__(16) __nv_bfloat16 g_avhi[8192ull * 1024];      // attn out
__device__ __align__(16) __nv_bfloat16 g_avlo[8192ull * 1024];
// Pre-split attention K/V. hb = head*4 + batch.
__device__ __align__(16) __nv_bfloat16 g_khi [16ull * 4 * 2048 * 64];   // [hb][l][d]
__device__ __align__(16) __nv_bfloat16 g_klo [16ull * 4 * 2048 * 64];
__device__ __align__(16) __nv_bfloat16 g_vthi[16ull * 4 * 64 * 2048];   // [hb][d][l]
__device__ __align__(16) __nv_bfloat16 g_vtlo[16ull * 4 * 64 * 2048];

// ============================================================================
// PTX helpers (sm_80-era ISA — compiles for plain compute_103)
// ============================================================================
__device__ __forceinline__ uint32_t smem_u32(const void* p) {
    uint32_t a;
    asm("{ .reg .u64 t; cvta.to.shared.u64 t, %1; cvt.u32.u64 %0, t; }"
        : "=r"(a) : "l"(p));
    return a;
}

__device__ __forceinline__ void ldmatrix_x4(uint32_t& r0, uint32_t& r1,
                                            uint32_t& r2, uint32_t& r3,
                                            uint32_t addr) {
    asm volatile("ldmatrix.sync.aligned.m8n8.x4.shared.b16 {%0,%1,%2,%3}, [%4];"
                 : "=r"(r0), "=r"(r1), "=r"(r2), "=r"(r3) : "r"(addr));
}

__device__ __forceinline__ void mma_bf16(float* c,
                                         uint32_t a0, uint32_t a1, uint32_t a2, uint32_t a3,
                                         uint32_t b0, uint32_t b1) {
    asm volatile("mma.sync.aligned.m16n8k16.row.col.f32.bf16.bf16.f32 "
                 "{%0,%1,%2,%3}, {%4,%5,%6,%7}, {%8,%9}, {%0,%1,%2,%3};"
                 : "+f"(c[0]), "+f"(c[1]), "+f"(c[2]), "+f"(c[3])
                 : "r"(a0), "r"(a1), "r"(a2), "r"(a3), "r"(b0), "r"(b1));
}

__device__ __forceinline__ void cp_async16(uint32_t dst, const void* src) {
    asm volatile("cp.async.cg.shared.global [%0], [%1], 16;"
                 :: "r"(dst), "l"(src) : "memory");
}
__device__ __forceinline__ void cp_commit() {
    asm volatile("cp.async.commit_group;" ::: "memory");
}
template <int N>
__device__ __forceinline__ void cp_wait() {
    asm volatile("cp.async.wait_group %0;" :: "n"(N) : "memory");
}

__device__ __forceinline__ uint32_t pack_bf16x2(float x, float y) {
    uint32_t r;
    asm("cvt.rn.bf16x2.f32 %0, %1, %2;" : "=r"(r) : "f"(y), "f"(x));
    return r;
}

// fast 2^t for t <= 0, FFMA/ALU only (no MUFU). rel err ~2.5e-6.
__device__ __forceinline__ float exp2_fast(float t) {
    float r = fmaxf(t, -30.f);
    float z = r + 12582912.f;
    int   i = __float_as_int(z);
    float f = r - (z - 12582912.f);
    float p = 1.33335581e-3f;
    p = fmaf(p, f, 9.61812911e-3f);
    p = fmaf(p, f, 5.55041087e-2f);
    p = fmaf(p, f, 2.40226507e-1f);
    p = fmaf(p, f, 6.93147181e-1f);
    p = fmaf(p, f, 1.0f);
    return p * __int_as_float((i + 127) << 23);
}

__device__ __forceinline__ void split4(float4 v, uint32_t& h01, uint32_t& h23,
                                       uint32_t& l01, uint32_t& l23) {
    h01 = pack_bf16x2(v.x, v.y);
    h23 = pack_bf16x2(v.z, v.w);
    float r0 = v.x - __int_as_float(h01 << 16);
    float r1 = v.y - __int_as_float(h01 & 0xFFFF0000u);
    float r2 = v.z - __int_as_float(h23 << 16);
    float r3 = v.w - __int_as_float(h23 & 0xFFFF0000u);
    l01 = pack_bf16x2(r0, r1);
    l23 = pack_bf16x2(r2, r3);
}

// ============================================================================
// Prep kernels (run once per launch; pure bandwidth)
// ============================================================================
__global__ __launch_bounds__(256) void prep_x(const float* __restrict__ x) {
    #pragma unroll
    for (int i = 0; i < 4; ++i) {
        size_t idx = (size_t)blockIdx.x * 256 + threadIdx.x + (size_t)i * 524288;
        float4 v = *(const float4*)(x + idx * 4);
        uint32_t h01, h23, l01, l23;
        split4(v, h01, h23, l01, l23);
        *(uint2*)&g_xhi[idx * 4] = make_uint2(h01, h23);
        *(uint2*)&g_xlo[idx * 4] = make_uint2(l01, l23);
    }
}

__global__ __launch_bounds__(256) void split_wp(const float* __restrict__ Wp) {
    #pragma unroll
    for (int i = 0; i < 4; ++i) {
        size_t idx = (size_t)blockIdx.x * 256 + threadIdx.x + (size_t)i * 65536;
        float4 v = *(const float4*)(Wp + idx * 4);
        uint32_t h01, h23, l01, l23;
        split4(v, h01, h23, l01, l23);
        *(uint2*)&g_wphi[idx * 4] = make_uint2(h01, h23);
        *(uint2*)&g_wplo[idx * 4] = make_uint2(l01, l23);
    }
}

// transpose Wqkv [48][1024][64] -> split bf16 [48][64][1024]
__global__ void transpose_w(const float* __restrict__ W) {
    __shared__ float t[32][33];
    const int e  = blockIdx.z;
    const int k0 = blockIdx.x * 32;
    const int h0 = blockIdx.y * 32;
    const int tx = threadIdx.x, ty = threadIdx.y;
    #pragma unroll
    for (int i = 0; i < 32; i += 8)
        t[ty + i][tx] = W[(size_t)e * 65536 + (size_t)(k0 + ty + i) * 64 + h0 + tx];
    __syncthreads();
    #pragma unroll
    for (int i = 0; i < 32; i += 8) {
        float val = t[tx][ty + i];
        __nv_bfloat16 hi = __float2bfloat16(val);
        __nv_bfloat16 lo = __float2bfloat16(val - __bfloat162float(hi));
        size_t off = (size_t)e * 65536 + (size_t)(h0 + ty + i) * 1024 + k0 + tx;
        g_wthi[off] = hi;
        g_wtlo[off] = lo;
    }
}

// prep K/V: split ctx K/V to bf16 hi/lo; V transposed to [d][l].
__global__ __launch_bounds__(256)
void prep_kv()
{
    __shared__ __nv_bfloat16 vt_hi[64 * 72];
    __shared__ __nv_bfloat16 vt_lo[64 * 72];

    const int tid = threadIdx.x;
    const int hb  = blockIdx.y;
    const int hd  = hb >> 2;
    const int b   = hb & 3;
    const int l0  = blockIdx.x * 64;

    const float* Kg = g_ctx + ((size_t)(16 + hd) * 8192 + (size_t)b * 2048 + l0) * 64;
    const float* Vg = g_ctx + ((size_t)(32 + hd) * 8192 + (size_t)b * 2048 + l0) * 64;

    #pragma unroll
    for (int i = 0; i < 4; ++i) {
        int idx = tid + i * 256;
        int row = idx >> 4;
        int c4  = idx & 15;
        float4 v = *(const float4*)(Kg + (size_t)row * 64 + c4 * 4);
        uint32_t h01, h23, l01, l23;
        split4(v, h01, h23, l01, l23);
        size_t off = ((size_t)hb * 2048 + l0 + row) * 64 + c4 * 4;
        *(uint2*)&g_khi[off] = make_uint2(h01, h23);
        *(uint2*)&g_klo[off] = make_uint2(l01, l23);
    }

    #pragma unroll
    for (int i = 0; i < 4; ++i) {
        int idx = tid + i * 256;
        int key = idx >> 4;
        int c4  = idx & 15;
        float4 v = *(const float4*)(Vg + (size_t)key * 64 + c4 * 4);
        uint32_t h01, h23, l01, l23;
        split4(v, h01, h23, l01, l23);
        int d = c4 * 4;
        vt_hi[(d + 0) * 72 + key] = __ushort_as_bfloat16((uint16_t)(h01 & 0xFFFF));
        vt_hi[(d + 1) * 72 + key] = __ushort_as_bfloat16((uint16_t)(h01 >> 16));
        vt_hi[(d + 2) * 72 + key] = __ushort_as_bfloat16((uint16_t)(h23 & 0xFFFF));
        vt_hi[(d + 3) * 72 + key] = __ushort_as_bfloat16((uint16_t)(h23 >> 16));
        vt_lo[(d + 0) * 72 + key] = __ushort_as_bfloat16((uint16_t)(l01 & 0xFFFF));
        vt_lo[(d + 1) * 72 + key] = __ushort_as_bfloat16((uint16_t)(l01 >> 16));
        vt_lo[(d + 2) * 72 + key] = __ushort_as_bfloat16((uint16_t)(l23 & 0xFFFF));
        vt_lo[(d + 3) * 72 + key] = __ushort_as_bfloat16((uint16_t)(l23 >> 16));
    }
    __syncthreads();

    #pragma unroll
    for (int i = 0; i < 2; ++i) {
        int idx = tid + i * 256;
        int d   = idx >> 3;
        int c   = idx & 7;
        uint4 hv = *(uint4*)&vt_hi[d * 72 + c * 8];
        uint4 lv = *(uint4*)&vt_lo[d * 72 + c * 8];
        size_t off = ((size_t)hb * 64 + d) * 2048 + l0 + c * 8;
        *(uint4*)&g_vthi[off] = hv;
        *(uint4*)&g_vtlo[off] = lv;
    }
}

// ============================================================================
// gemm_bf: pre-split bf16 GEMM, cp.async 3-stage, 1 sync per k-chunk.
//   C[grp][m][n] = sum_k A[m][k]*B[grp*64+n][k] + bias[grp*64+n]
//   CTA 128x64, 8 warps (4m x 2n), BK=32.
// ============================================================================
#define LDA 80u
#define G_AHI 0u
#define G_ALO 10240u
#define G_BHI 20480u
#define G_BLO 25600u
#define G_STG 30720u
#define GEMM_SMEM (3 * 30720)

__global__ __launch_bounds__(256)
void gemm_bf(const __nv_bfloat16* __restrict__ Ahi, const __nv_bfloat16* __restrict__ Alo,
             const __nv_bfloat16* __restrict__ Bhi, const __nv_bfloat16* __restrict__ Blo,
             const float* __restrict__ bias, float* __restrict__ C,
             int ldC, size_t gStrideC)
{
    extern __shared__ __align__(128) char smem[];
    const uint32_t sb  = smem_u32(smem);
    const int tid  = threadIdx.x;
    const int lane = tid & 31;
    const int wid  = tid >> 5;
    const int wm   = wid & 3;
    const int wn   = wid >> 2;
    const int m0   = blockIdx.x * 128;
    const int grp  = blockIdx.y;

    const __nv_bfloat16* Bhig = Bhi + (size_t)grp * 64 * 1024;
    const __nv_bfloat16* Blog = Blo + (size_t)grp * 64 * 1024;

    float acc[2][4][4];
    #pragma unroll
    for (int mt = 0; mt < 2; ++mt)
        #pragma unroll
        for (int nt = 0; nt < 4; ++nt)
            #pragma unroll
            for (int i = 0; i < 4; ++i) acc[mt][nt][i] = 0.f;

    const int cp_r = tid >> 2;      // 0..63
    const int cp_c = tid & 3;       // 16B granule within 64B row
    auto issue = [&](int ks, uint32_t stg) {
        const int k0 = ks * 32;
        const int ce = cp_c * 8;
        uint32_t d0 = stg + (uint32_t)cp_r * LDA + (uint32_t)cp_c * 16u;
        uint32_t d1 = stg + (uint32_t)(cp_r + 64) * LDA + (uint32_t)cp_c * 16u;
        size_t a0 = (size_t)(m0 + cp_r) * 1024 + k0 + ce;
        size_t a1 = (size_t)(m0 + cp_r + 64) * 1024 + k0 + ce;
        size_t b0 = (size_t)cp_r * 1024 + k0 + ce;
        cp_async16(d0 + G_AHI, Ahi + a0);
        cp_async16(d1 + G_AHI, Ahi + a1);
        cp_async16(d0 + G_ALO, Alo + a0);
        cp_async16(d1 + G_ALO, Alo + a1);
        cp_async16(d0 + G_BHI, Bhig + b0);
        cp_async16(d0 + G_BLO, Blog + b0);
        cp_commit();
    };

    const uint32_t a_row = (uint32_t)(wm * 32 + (lane & 7) + ((lane >> 3) & 1) * 8);
    const uint32_t a_kb  = (uint32_t)(lane >> 4) * 16u;
    const uint32_t b_row = (uint32_t)(wn * 32 + (lane & 7) + (lane >> 4) * 8);
    const uint32_t b_kb  = (uint32_t)((lane >> 3) & 1) * 16u;

    issue(0, sb);
    issue(1, sb + G_STG);

    for (int ks = 0; ks < 32; ++ks) {
        if (ks < 31) cp_wait<1>(); else cp_wait<0>();
        __syncthreads();
        if (ks + 2 < 32) issue(ks + 2, sb + (uint32_t)((ks + 2) % 3) * G_STG);

        const uint32_t stg = sb + (uint32_t)(ks % 3) * G_STG;
        const uint32_t aHi = stg + G_AHI + a_row * LDA + a_kb;
        const uint32_t aLo = stg + G_ALO + a_row * LDA + a_kb;
        const uint32_t bHi = stg + G_BHI + b_row * LDA + b_kb;
        const uint32_t bLo = stg + G_BLO + b_row * LDA + b_kb;

        #pragma unroll
        for (int kk = 0; kk < 2; ++kk) {
            const uint32_t koff = (uint32_t)kk * 32u;

            uint32_t ahi[2][4], alo[2][4];
            #pragma unroll
            for (int mt = 0; mt < 2; ++mt) {
                ldmatrix_x4(ahi[mt][0], ahi[mt][1], ahi[mt][2], ahi[mt][3],
                            aHi + (uint32_t)mt * 16u * LDA + koff);
                ldmatrix_x4(alo[mt][0], alo[mt][1], alo[mt][2], alo[mt][3],
                            aLo + (uint32_t)mt * 16u * LDA + koff);
            }
            uint32_t bhi[4][2], blo[4][2];
            #pragma unroll
            for (int ntp = 0; ntp < 2; ++ntp) {
                uint32_t r0, r1, r2, r3;
                ldmatrix_x4(r0, r1, r2, r3, bHi + (uint32_t)ntp * 16u * LDA + koff);
                bhi[ntp * 2][0] = r0; bhi[ntp * 2][1] = r1;
                bhi[ntp * 2 + 1][0] = r2; bhi[ntp * 2 + 1][1] = r3;
                ldmatrix_x4(r0, r1, r2, r3, bLo + (uint32_t)ntp * 16u * LDA + koff);
                blo[ntp * 2][0] = r0; blo[ntp * 2][1] = r1;
                blo[ntp * 2 + 1][0] = r2; blo[ntp * 2 + 1][1] = r3;
            }

            #pragma unroll
            for (int mt = 0; mt < 2; ++mt)
                #pragma unroll
                for (int nt = 0; nt < 4; ++nt) {
                    mma_bf16(acc[mt][nt], ahi[mt][0], ahi[mt][1], ahi[mt][2], ahi[mt][3],
                             bhi[nt][0], bhi[nt][1]);
                    mma_bf16(acc[mt][nt], ahi[mt][0], ahi[mt][1], ahi[mt][2], ahi[mt][3],
                             blo[nt][0], blo[nt][1]);
                    mma_bf16(acc[mt][nt], alo[mt][0], alo[mt][1], alo[mt][2], alo[mt][3],
                             bhi[nt][0], bhi[nt][1]);
                }
        }
    }

    const int g  = lane >> 2;
    const int tg = lane & 3;
    const float* bp = bias + (size_t)grp * 64;
    float* Cp = C + (size_t)grp * gStrideC;
    #pragma unroll
    for (int mt = 0; mt < 2; ++mt)
        #pragma unroll
        for (int nt = 0; nt < 4; ++nt) {
            int col = wn * 32 + nt * 8 + tg * 2;
            float b0 = bp[col], b1 = bp[col + 1];
            int r0 = m0 + wm * 32 + mt * 16 + g;
            float2 o0 = make_float2(acc[mt][nt][0] + b0, acc[mt][nt][1] + b1);
            float2 o1 = make_float2(acc[mt][nt][2] + b0, acc[mt][nt][3] + b1);
            *(float2*)(Cp + (size_t)r0 * ldC + col)       = o0;
            *(float2*)(Cp + (size_t)(r0 + 8) * ldC + col) = o1;
        }
}

// ============================================================================
// attn_mma: tensor-core flash attention, 3-stage cp.async, 1 sync per chunk.
//   Epilogue writes pre-split av (bf16 hi/lo) for proj.
// ============================================================================
#define LDS_ROW 144u
#define ST_KHI 0u
#define ST_KLO 9216u
#define ST_VHI 18432u
#define ST_VLO 27648u
#define STAGE_BYTES 36864u
#define ATTN_SMEM (3 * 36864)

__global__ __launch_bounds__(256)
void attn_mma()
{
    extern __shared__ __align__(128) char smem[];
    const uint32_t sb = smem_u32(smem);
    const int tid  = threadIdx.x;
    const int lane = tid & 31;
    const int wid  = tid >> 5;
    const int g    = lane >> 2;
    const int tg   = lane & 3;
    const int hb   = blockIdx.y;
    const int hd   = hb >> 2;
    const int b    = hb & 3;
    const int q0   = blockIdx.x * 128;

    const float* Qg = g_ctx + ((size_t)hd * 8192 + b * 2048 + q0) * 64;
    const __nv_bfloat16* Khi = g_khi  + (size_t)hb * 2048 * 64;
    const __nv_bfloat16* Klo = g_klo  + (size_t)hb * 2048 * 64;
    const __nv_bfloat16* Vhi = g_vthi + (size_t)hb * 64 * 2048;
    const __nv_bfloat16* Vlo = g_vtlo + (size_t)hb * 64 * 2048;

    // ---- stage Q (scaled by 8*log2e), split, extract fragments ----
    const float QSCALE = 11.5415603272f;   // 8 / ln(2)
    #pragma unroll
    for (int i = 0; i < 8; ++i) {
        int idx = tid + i * 256;
        int row = idx >> 4;
        int c4  = idx & 15;
        float4 v = *(const float4*)(Qg + (size_t)row * 64 + c4 * 4);
        v.x *= QSCALE; v.y *= QSCALE; v.z *= QSCALE; v.w *= QSCALE;
        uint32_t h01, h23, l01, l23;
        split4(v, h01, h23, l01, l23);
        uint32_t off = (uint32_t)row * LDS_ROW + (uint32_t)c4 * 8u;
        *(uint2*)(smem + off)         = make_uint2(h01, h23);
        *(uint2*)(smem + 18432 + off) = make_uint2(l01, l23);
    }
    __syncthreads();

    uint32_t qhi[4][4], qlo[4][4];
    {
        const uint32_t qrow = (uint32_t)(wid * 16 + (lane & 7) + ((lane >> 3) & 1) * 8);
        const uint32_t kb   = (uint32_t)(lane >> 4) * 16u;
        const uint32_t aH = sb + qrow * LDS_ROW + kb;
        const uint32_t aL = sb + 18432 + qrow * LDS_ROW + kb;
        #pragma unroll
        for (int t = 0; t < 4; ++t) {
            ldmatrix_x4(qhi[t][0], qhi[t][1], qhi[t][2], qhi[t][3], aH + t * 32u);
            ldmatrix_x4(qlo[t][0], qlo[t][1], qlo[t][2], qlo[t][3], aL + t * 32u);
        }
    }
    __syncthreads();   // Q consumed — smem free for stages

    float mA = -1e30f, mB = -1e30f, lA = 0.f, lB = 0.f;
    float oacc[8][4];
    #pragma unroll
    for (int j = 0; j < 8; ++j)
        #pragma unroll
        for (int i = 0; i < 4; ++i) oacc[j][i] = 0.f;

    const uint32_t brow = (uint32_t)((lane & 7) + (lane >> 4) * 8);
    const uint32_t bkb  = (uint32_t)((lane >> 3) & 1) * 16u;

    const int cp_row = tid >> 3;     // 0..31
    const int cp_c   = tid & 7;      // 16B granule
    auto issue = [&](int j0, uint32_t stg) {
        #pragma unroll
        for (int i = 0; i < 2; ++i) {
            int row = cp_row + i * 32;
            uint32_t doff = stg + (uint32_t)row * LDS_ROW + (uint32_t)cp_c * 16u;
            cp_async16(doff + ST_KHI, Khi + ((size_t)(j0 + row)) * 64 + cp_c * 8);
            cp_async16(doff + ST_KLO, Klo + ((size_t)(j0 + row)) * 64 + cp_c * 8);
            cp_async16(doff + ST_VHI, Vhi + ((size_t)row) * 2048 + j0 + cp_c * 8);
            cp_async16(doff + ST_VLO, Vlo + ((size_t)row) * 2048 + j0 + cp_c * 8);
        }
        cp_commit();
    };

    issue(0, sb);
    issue(64, sb + STAGE_BYTES);

    for (int j = 0; j < 32; ++j) {
        if (j < 31) cp_wait<1>(); else cp_wait<0>();
        __syncthreads();
        if (j + 2 < 32) issue((j + 2) * 64, sb + (uint32_t)((j + 2) % 3) * STAGE_BYTES);

        const uint32_t stg = sb + (uint32_t)(j % 3) * STAGE_BYTES;

        // ---- S = Qscaled @ K^T (split 3-term), log2 units ----
        float sacc[8][4];
        #pragma unroll
        for (int jj = 0; jj < 8; ++jj)
            #pragma unroll
            for (int i = 0; i < 4; ++i) sacc[jj][i] = 0.f;

        #pragma unroll
        for (int td = 0; td < 4; ++td) {
            uint32_t bhi[8][2], blo[8][2];
            #pragma unroll
            for (int ntp = 0; ntp < 4; ++ntp) {
                uint32_t base = (uint32_t)(ntp * 16) * LDS_ROW + brow * LDS_ROW + bkb
                                + (uint32_t)td * 32u;
                uint32_t r0, r1, r2, r3;
                ldmatrix_x4(r0, r1, r2, r3, stg + ST_KHI + base);
                bhi[ntp * 2][0] = r0; bhi[ntp * 2][1] = r1;
                bhi[ntp * 2 + 1][0] = r2; bhi[ntp * 2 + 1][1] = r3;
                ldmatrix_x4(r0, r1, r2, r3, stg + ST_KLO + base);
                blo[ntp * 2][0] = r0; blo[ntp * 2][1] = r1;
                blo[ntp * 2 + 1][0] = r2; blo[ntp * 2 + 1][1] = r3;
            }
            #pragma unroll
            for (int nt = 0; nt < 8; ++nt) {
                mma_bf16(sacc[nt], qhi[td][0], qhi[td][1], qhi[td][2], qhi[td][3],
                         bhi[nt][0], bhi[nt][1]);
                mma_bf16(sacc[nt], qhi[td][0], qhi[td][1], qhi[td][2], qhi[td][3],
                         blo[nt][0], blo[nt][1]);
                mma_bf16(sacc[nt], qlo[td][0], qlo[td][1], qlo[td][2], qlo[td][3],
                         bhi[nt][0], bhi[nt][1]);
            }
        }

        // ---- online softmax (log2 domain) ----
        float rmA = -1e30f, rmB = -1e30f;
        #pragma unroll
        for (int jj = 0; jj < 8; ++jj) {
            rmA = fmaxf(rmA, fmaxf(sacc[jj][0], sacc[jj][1]));
            rmB = fmaxf(rmB, fmaxf(sacc[jj][2], sacc[jj][3]));
        }
        rmA = fmaxf(rmA, __shfl_xor_sync(0xffffffffu, rmA, 1));
        rmA = fmaxf(rmA, __shfl_xor_sync(0xffffffffu, rmA, 2));
        rmB = fmaxf(rmB, __shfl_xor_sync(0xffffffffu, rmB, 1));
        rmB = fmaxf(rmB, __shfl_xor_sync(0xffffffffu, rmB, 2));

        float mnA = fmaxf(mA, rmA), mnB = fmaxf(mB, rmB);
        float corrA = exp2_fast(mA - mnA), corrB = exp2_fast(mB - mnB);

        float sumA = 0.f, sumB = 0.f;
        uint32_t phi[4][4], plo[4][4];
        #pragma unroll
        for (int jj = 0; jj < 8; ++jj) {
            float p0 = exp2_fast(sacc[jj][0] - mnA);
            float p1 = exp2_fast(sacc[jj][1] - mnA);
            float p2 = exp2_fast(sacc[jj][2] - mnB);
            float p3 = exp2_fast(sacc[jj][3] - mnB);
            sumA += p0 + p1; sumB += p2 + p3;
            int t = jj >> 1;
            int o = (jj & 1) * 2;
            uint32_t h01 = pack_bf16x2(p0, p1);
            uint32_t h23 = pack_bf16x2(p2, p3);
            phi[t][o]     = h01;
            phi[t][o + 1] = h23;
            float r0 = p0 - __int_as_float(h01 << 16);
            float r1 = p1 - __int_as_float(h01 & 0xFFFF0000u);
            float r2 = p2 - __int_as_float(h23 << 16);
            float r3 = p3 - __int_as_float(h23 & 0xFFFF0000u);
            plo[t][o]     = pack_bf16x2(r0, r1);
            plo[t][o + 1] = pack_bf16x2(r2, r3);
        }
        sumA += __shfl_xor_sync(0xffffffffu, sumA, 1);
        sumA += __shfl_xor_sync(0xffffffffu, sumA, 2);
        sumB += __shfl_xor_sync(0xffffffffu, sumB, 1);
        sumB += __shfl_xor_sync(0xffffffffu, sumB, 2);

        lA = lA * corrA + sumA;
        lB = lB * corrB + sumB;
        mA = mnA; mB = mnB;

        #pragma unroll
        for (int jj = 0; jj < 8; ++jj) {
            oacc[jj][0] *= corrA; oacc[jj][1] *= corrA;
            oacc[jj][2] *= corrB; oacc[jj][3] *= corrB;
        }

        // ---- O += P @ V (split 3-term) ----
        #pragma unroll
        for (int t = 0; t < 4; ++t) {
            uint32_t vhi[8][2], vlo[8][2];
            #pragma unroll
            for (int ntp = 0; ntp < 4; ++ntp) {
                uint32_t base = (uint32_t)(ntp * 16) * LDS_ROW + brow * LDS_ROW + bkb
                                + (uint32_t)t * 32u;
                uint32_t r0, r1, r2, r3;
                ldmatrix_x4(r0, r1, r2, r3, stg + ST_VHI + base);
                vhi[ntp * 2][0] = r0; vhi[ntp * 2][1] = r1;
                vhi[ntp * 2 + 1][0] = r2; vhi[ntp * 2 + 1][1] = r3;
                ldmatrix_x4(r0, r1, r2, r3, stg + ST_VLO + base);
                vlo[ntp * 2][0] = r0; vlo[ntp * 2][1] = r1;
                vlo[ntp * 2 + 1][0] = r2; vlo[ntp * 2 + 1][1] = r3;
            }
            #pragma unroll
            for (int nd = 0; nd < 8; ++nd) {
                mma_bf16(oacc[nd], phi[t][0], phi[t][1], phi[t][2], phi[t][3],
                         vhi[nd][0], vhi[nd][1]);
                mma_bf16(oacc[nd], phi[t][0], phi[t][1], phi[t][2], phi[t][3],
                         vlo[nd][0], vlo[nd][1]);
                mma_bf16(oacc[nd], plo[t][0], plo[t][1], plo[t][2], plo[t][3],
                         vhi[nd][0], vhi[nd][1]);
            }
        }
    }

    // ---- epilogue: normalize, split to bf16 hi/lo, write g_avhi/g_avlo ----
    const float invA = 1.f / lA, invB = 1.f / lB;
    const int rowA = q0 + wid * 16 + g;
    const int rowB = rowA + 8;
    #pragma unroll
    for (int jd = 0; jd < 8; ++jd) {
        int col = hd * 64 + jd * 8 + tg * 2;
        {
            float o0 = oacc[jd][0] * invA, o1 = oacc[jd][1] * invA;
            uint32_t h = pack_bf16x2(o0, o1);
            float r0 = o0 - __int_as_float(h << 16);
            float r1 = o1 - __int_as_float(h & 0xFFFF0000u);
            uint32_t l = pack_bf16x2(r0, r1);
            size_t base = (size_t)(b * 2048 + rowA) * 1024 + col;
            *(uint32_t*)&g_avhi[base] = h;
            *(uint32_t*)&g_avlo[base] = l;
        }
        {
            float o2 = oacc[jd][2] * invB, o3 = oacc[jd][3] * invB;
            uint32_t h = pack_bf16x2(o2, o3);
            float r2 = o2 - __int_as_float(h << 16);
            float r3 = o3 - __int_as_float(h & 0xFFFF0000u);
            uint32_t l = pack_bf16x2(r2, r3);
            size_t base = (size_t)(b * 2048 + rowB) * 1024 + col;
            *(uint32_t*)&g_avhi[base] = h;
            *(uint32_t*)&g_avlo[base] = l;
        }
    }
}

// ============================================================================
extern "C" void kernel_launch(void* const* d_in, const int* in_sizes, int n_in,
                              void* d_out, int out_size)
{
    const float* x    = (const float*)d_in[0];   // (4, 2048, 1024)
    const float* Wqkv = (const float*)d_in[1];   // (48, 1024, 64)
    const float* bqkv = (const float*)d_in[2];   // (48, 64)
    const float* Wp   = (const float*)d_in[3];   // (1024, 1024)
    const float* bp   = (const float*)d_in[4];   // (1024,)
    float* out = (float*)d_out;                  // (4, 2048, 1024)

    float* g_ctx_p;  cudaGetSymbolAddress((void**)&g_ctx_p, g_ctx);
    __nv_bfloat16 *xhi, *xlo, *wthi, *wtlo, *wphi, *wplo, *avhi, *avlo;
    cudaGetSymbolAddress((void**)&xhi,  g_xhi);
    cudaGetSymbolAddress((void**)&xlo,  g_xlo);
    cudaGetSymbolAddress((void**)&wthi, g_wthi);
    cudaGetSymbolAddress((void**)&wtlo, g_wtlo);
    cudaGetSymbolAddress((void**)&wphi, g_wphi);
    cudaGetSymbolAddress((void**)&wplo, g_wplo);
    cudaGetSymbolAddress((void**)&avhi, g_avhi);
    cudaGetSymbolAddress((void**)&avlo, g_avlo);

    // No static guards (harness rule): set attributes unconditionally.
    // These are not stream operations and are graph-capture safe.
    cudaFuncSetAttribute(gemm_bf, cudaFuncAttributeMaxDynamicSharedMemorySize,
                         GEMM_SMEM);
    cudaFuncSetAttribute(attn_mma, cudaFuncAttributeMaxDynamicSharedMemorySize,
                         ATTN_SMEM);

    // 1) preps: split x, Wp; transpose+split Wqkv
    prep_x<<<2048, 256>>>(x);
    split_wp<<<256, 256>>>(Wp);
    transpose_w<<<dim3(32, 2, 48), dim3(32, 8)>>>(Wqkv);

    // 2) QKV: ctx[e] = x @ Wqkv[e]^T(+split) + bqkv[e]
    gemm_bf<<<dim3(64, 48), 256, GEMM_SMEM>>>(xhi, xlo, wthi, wtlo, bqkv, g_ctx_p,
                                              /*ldC=*/64,
                                              /*gStrideC=*/(size_t)8192 * 64);

    // 2.5) pre-split K/V (V transposed)
    prep_kv<<<dim3(32, 64), 256>>>();

    // 3) attention (3-stage cp.async; epilogue emits split av)
    attn_mma<<<dim3(16, 64), 256, ATTN_SMEM>>>();

    // 4) proj: out = av @ Wp^T + bp
    gemm_bf<<<dim3(64, 16), 256, GEMM_SMEM>>>(avhi, avlo, wphi, wplo, bp, out,
                                              /*ldC=*/1024, /*gStrideC=*/64);
}

// round 9
// speedup vs baseline: 1.0139x; 1.0139x over previous
#include <cuda_runtime.h>
#include <cuda_bf16.h>
#include <stdint.h>
#include <math.h>

// ============================================================================
// Scratch (device globals — no allocations allowed).
// ============================================================================
__device__ float g_ctx[48ull * 8192ull * 64ull];   // [e][row][h], ~100.7 MB
__device__ __align__(16) __nv_bfloat16 g_xhi [8192ull * 1024];
__device__ __align__(16) __nv_bfloat16 g_xlo [8192ull * 1024];
__device__ __align__(16) __nv_bfloat16 g_wthi[48ull * 64 * 1024];   // Wqkv^T [e][h][d]
__device__ __align__(16) __nv_bfloat16 g_wtlo[48ull * 64 * 1024];
__device__ __align__(16) __nv_bfloat16 g_wphi[1024ull * 1024];      // Wp [n][k]
__device__ __align__(16) __nv_bfloat16 g_wplo[1024ull * 1024];
__device__ __align__(16) __nv_bfloat16 g_avhi[8192ull * 1024];
__device__ __align__(16) __nv_bfloat16 g_avlo[8192ull * 1024];
__device__ __align__(16) __nv_bfloat16 g_khi [16ull * 4 * 2048 * 64];   // [hb][l][d]
__device__ __align__(16) __nv_bfloat16 g_klo [16ull * 4 * 2048 * 64];
__device__ __align__(16) __nv_bfloat16 g_vthi[16ull * 4 * 64 * 2048];   // [hb][d][l]
__device__ __align__(16) __nv_bfloat16 g_vtlo[16ull * 4 * 64 * 2048];

// ============================================================================
// PTX helpers (sm_80-era ISA — compiles for plain compute_103)
// ============================================================================
__device__ __forceinline__ uint32_t smem_u32(const void* p) {
    uint32_t a;
    asm("{ .reg .u64 t; cvta.to.shared.u64 t, %1; cvt.u32.u64 %0, t; }"
        : "=r"(a) : "l"(p));
    return a;
}

__device__ __forceinline__ void ldmatrix_x4(uint32_t& r0, uint32_t& r1,
                                            uint32_t& r2, uint32_t& r3,
                                            uint32_t addr) {
    asm volatile("ldmatrix.sync.aligned.m8n8.x4.shared.b16 {%0,%1,%2,%3}, [%4];"
                 : "=r"(r0), "=r"(r1), "=r"(r2), "=r"(r3) : "r"(addr));
}

__device__ __forceinline__ void mma_bf16(float* c,
                                         uint32_t a0, uint32_t a1, uint32_t a2, uint32_t a3,
                                         uint32_t b0, uint32_t b1) {
    asm volatile("mma.sync.aligned.m16n8k16.row.col.f32.bf16.bf16.f32 "
                 "{%0,%1,%2,%3}, {%4,%5,%6,%7}, {%8,%9}, {%0,%1,%2,%3};"
                 : "+f"(c[0]), "+f"(c[1]), "+f"(c[2]), "+f"(c[3])
                 : "r"(a0), "r"(a1), "r"(a2), "r"(a3), "r"(b0), "r"(b1));
}

__device__ __forceinline__ void cp_async16(uint32_t dst, const void* src) {
    asm volatile("cp.async.cg.shared.global [%0], [%1], 16;"
                 :: "r"(dst), "l"(src) : "memory");
}
__device__ __forceinline__ void cp_commit() {
    asm volatile("cp.async.commit_group;" ::: "memory");
}
template <int N>
__device__ __forceinline__ void cp_wait() {
    asm volatile("cp.async.wait_group %0;" :: "n"(N) : "memory");
}

__device__ __forceinline__ uint32_t pack_bf16x2(float x, float y) {
    uint32_t r;
    asm("cvt.rn.bf16x2.f32 %0, %1, %2;" : "=r"(r) : "f"(y), "f"(x));
    return r;
}

// fast 2^t for t <= 0, FFMA/ALU only (no MUFU). rel err ~2.5e-6.
__device__ __forceinline__ float exp2_fast(float t) {
    float r = fmaxf(t, -30.f);
    float z = r + 12582912.f;
    int   i = __float_as_int(z);
    float f = r - (z - 12582912.f);
    float p = 1.33335581e-3f;
    p = fmaf(p, f, 9.61812911e-3f);
    p = fmaf(p, f, 5.55041087e-2f);
    p = fmaf(p, f, 2.40226507e-1f);
    p = fmaf(p, f, 6.93147181e-1f);
    p = fmaf(p, f, 1.0f);
    return p * __int_as_float((i + 127) << 23);
}

__device__ __forceinline__ void split4(float4 v, uint32_t& h01, uint32_t& h23,
                                       uint32_t& l01, uint32_t& l23) {
    h01 = pack_bf16x2(v.x, v.y);
    h23 = pack_bf16x2(v.z, v.w);
    float r0 = v.x - __int_as_float(h01 << 16);
    float r1 = v.y - __int_as_float(h01 & 0xFFFF0000u);
    float r2 = v.z - __int_as_float(h23 << 16);
    float r3 = v.w - __int_as_float(h23 & 0xFFFF0000u);
    l01 = pack_bf16x2(r0, r1);
    l23 = pack_bf16x2(r2, r3);
}

// ============================================================================
// Prep kernels
// ============================================================================
__global__ __launch_bounds__(256) void prep_x(const float* __restrict__ x) {
    #pragma unroll
    for (int i = 0; i < 4; ++i) {
        size_t idx = (size_t)blockIdx.x * 256 + threadIdx.x + (size_t)i * 524288;
        float4 v = *(const float4*)(x + idx * 4);
        uint32_t h01, h23, l01, l23;
        split4(v, h01, h23, l01, l23);
        *(uint2*)&g_xhi[idx * 4] = make_uint2(h01, h23);
        *(uint2*)&g_xlo[idx * 4] = make_uint2(l01, l23);
    }
}

__global__ __launch_bounds__(256) void split_wp(const float* __restrict__ Wp) {
    #pragma unroll
    for (int i = 0; i < 4; ++i) {
        size_t idx = (size_t)blockIdx.x * 256 + threadIdx.x + (size_t)i * 65536;
        float4 v = *(const float4*)(Wp + idx * 4);
        uint32_t h01, h23, l01, l23;
        split4(v, h01, h23, l01, l23);
        *(uint2*)&g_wphi[idx * 4] = make_uint2(h01, h23);
        *(uint2*)&g_wplo[idx * 4] = make_uint2(l01, l23);
    }
}

__global__ void transpose_w(const float* __restrict__ W) {
    __shared__ float t[32][33];
    const int e  = blockIdx.z;
    const int k0 = blockIdx.x * 32;
    const int h0 = blockIdx.y * 32;
    const int tx = threadIdx.x, ty = threadIdx.y;
    #pragma unroll
    for (int i = 0; i < 32; i += 8)
        t[ty + i][tx] = W[(size_t)e * 65536 + (size_t)(k0 + ty + i) * 64 + h0 + tx];
    __syncthreads();
    #pragma unroll
    for (int i = 0; i < 32; i += 8) {
        float val = t[tx][ty + i];
        __nv_bfloat16 hi = __float2bfloat16(val);
        __nv_bfloat16 lo = __float2bfloat16(val - __bfloat162float(hi));
        size_t off = (size_t)e * 65536 + (size_t)(h0 + ty + i) * 1024 + k0 + tx;
        g_wthi[off] = hi;
        g_wtlo[off] = lo;
    }
}

__global__ __launch_bounds__(256)
void prep_kv()
{
    __shared__ __nv_bfloat16 vt_hi[64 * 72];
    __shared__ __nv_bfloat16 vt_lo[64 * 72];

    const int tid = threadIdx.x;
    const int hb  = blockIdx.y;
    const int hd  = hb >> 2;
    const int b   = hb & 3;
    const int l0  = blockIdx.x * 64;

    const float* Kg = g_ctx + ((size_t)(16 + hd) * 8192 + (size_t)b * 2048 + l0) * 64;
    const float* Vg = g_ctx + ((size_t)(32 + hd) * 8192 + (size_t)b * 2048 + l0) * 64;

    #pragma unroll
    for (int i = 0; i < 4; ++i) {
        int idx = tid + i * 256;
        int row = idx >> 4;
        int c4  = idx & 15;
        float4 v = *(const float4*)(Kg + (size_t)row * 64 + c4 * 4);
        uint32_t h01, h23, l01, l23;
        split4(v, h01, h23, l01, l23);
        size_t off = ((size_t)hb * 2048 + l0 + row) * 64 + c4 * 4;
        *(uint2*)&g_khi[off] = make_uint2(h01, h23);
        *(uint2*)&g_klo[off] = make_uint2(l01, l23);
    }

    #pragma unroll
    for (int i = 0; i < 4; ++i) {
        int idx = tid + i * 256;
        int key = idx >> 4;
        int c4  = idx & 15;
        float4 v = *(const float4*)(Vg + (size_t)key * 64 + c4 * 4);
        uint32_t h01, h23, l01, l23;
        split4(v, h01, h23, l01, l23);
        int d = c4 * 4;
        vt_hi[(d + 0) * 72 + key] = __ushort_as_bfloat16((uint16_t)(h01 & 0xFFFF));
        vt_hi[(d + 1) * 72 + key] = __ushort_as_bfloat16((uint16_t)(h01 >> 16));
        vt_hi[(d + 2) * 72 + key] = __ushort_as_bfloat16((uint16_t)(h23 & 0xFFFF));
        vt_hi[(d + 3) * 72 + key] = __ushort_as_bfloat16((uint16_t)(h23 >> 16));
        vt_lo[(d + 0) * 72 + key] = __ushort_as_bfloat16((uint16_t)(l01 & 0xFFFF));
        vt_lo[(d + 1) * 72 + key] = __ushort_as_bfloat16((uint16_t)(l01 >> 16));
        vt_lo[(d + 2) * 72 + key] = __ushort_as_bfloat16((uint16_t)(l23 & 0xFFFF));
        vt_lo[(d + 3) * 72 + key] = __ushort_as_bfloat16((uint16_t)(l23 >> 16));
    }
    __syncthreads();

    #pragma unroll
    for (int i = 0; i < 2; ++i) {
        int idx = tid + i * 256;
        int d   = idx >> 3;
        int c   = idx & 7;
        uint4 hv = *(uint4*)&vt_hi[d * 72 + c * 8];
        uint4 lv = *(uint4*)&vt_lo[d * 72 + c * 8];
        size_t off = ((size_t)hb * 64 + d) * 2048 + l0 + c * 8;
        *(uint4*)&g_vthi[off] = hv;
        *(uint4*)&g_vtlo[off] = lv;
    }
}

// ============================================================================
// gemm_bf2: 128x128 CTA (2 groups of 64 cols), warp tile 64x32 (2m x 4n),
//   pre-split bf16, 3-stage cp.async, 1 sync per k-chunk. 32 FLOP/smem-byte.
// ============================================================================
#define LDA 80u
#define G2_AHI 0u
#define G2_ALO 10240u
#define G2_BHI 20480u
#define G2_BLO 30720u
#define G2_STG 40960u
#define GEMM_SMEM (3 * 40960)

__global__ __launch_bounds__(256)
void gemm_bf2(const __nv_bfloat16* __restrict__ Ahi, const __nv_bfloat16* __restrict__ Alo,
              const __nv_bfloat16* __restrict__ Bhi, const __nv_bfloat16* __restrict__ Blo,
              const float* __restrict__ bias, float* __restrict__ C,
              int ldC, size_t gStrideC)
{
    extern __shared__ __align__(128) char smem[];
    const uint32_t sb  = smem_u32(smem);
    const int tid  = threadIdx.x;
    const int lane = tid & 31;
    const int wid  = tid >> 5;
    const int wm   = wid & 1;        // 2 m-blocks of 64 rows
    const int wn   = wid >> 1;       // 4 n-blocks of 32 cols
    const int m0   = blockIdx.x * 128;
    const int grp0 = blockIdx.y * 2;

    const __nv_bfloat16* Bh0 = Bhi + (size_t)grp0 * 65536;
    const __nv_bfloat16* Bl0 = Blo + (size_t)grp0 * 65536;

    float acc[4][4][4];
    #pragma unroll
    for (int mt = 0; mt < 4; ++mt)
        #pragma unroll
        for (int nt = 0; nt < 4; ++nt)
            #pragma unroll
            for (int i = 0; i < 4; ++i) acc[mt][nt][i] = 0.f;

    const int cp_r = tid >> 2;      // 0..63
    const int cp_c = tid & 3;       // 16B granule within 64B row
    const int ce   = cp_c * 8;
    auto issue = [&](int ks, uint32_t stg) {
        const int k0 = ks * 32;
        uint32_t d0 = stg + (uint32_t)cp_r * LDA + (uint32_t)cp_c * 16u;
        uint32_t d1 = d0 + 64u * LDA;
        size_t a0 = (size_t)(m0 + cp_r) * 1024 + k0 + ce;
        size_t a1 = a0 + 64 * 1024;
        size_t b0 = (size_t)cp_r * 1024 + k0 + ce;
        cp_async16(d0 + G2_AHI, Ahi + a0);
        cp_async16(d1 + G2_AHI, Ahi + a1);
        cp_async16(d0 + G2_ALO, Alo + a0);
        cp_async16(d1 + G2_ALO, Alo + a1);
        cp_async16(d0 + G2_BHI, Bh0 + b0);
        cp_async16(d1 + G2_BHI, Bh0 + 65536 + b0);
        cp_async16(d0 + G2_BLO, Bl0 + b0);
        cp_async16(d1 + G2_BLO, Bl0 + 65536 + b0);
        cp_commit();
    };

    const uint32_t a_row = (uint32_t)(wm * 64 + (lane & 7) + ((lane >> 3) & 1) * 8);
    const uint32_t a_kb  = (uint32_t)(lane >> 4) * 16u;
    const uint32_t b_row = (uint32_t)(wn * 32 + (lane & 7) + (lane >> 4) * 8);
    const uint32_t b_kb  = (uint32_t)((lane >> 3) & 1) * 16u;

    issue(0, sb);
    issue(1, sb + G2_STG);

    for (int ks = 0; ks < 32; ++ks) {
        if (ks < 31) cp_wait<1>(); else cp_wait<0>();
        __syncthreads();
        if (ks + 2 < 32) issue(ks + 2, sb + (uint32_t)((ks + 2) % 3) * G2_STG);

        const uint32_t stg = sb + (uint32_t)(ks % 3) * G2_STG;
        const uint32_t aHi = stg + G2_AHI + a_row * LDA + a_kb;
        const uint32_t aLo = stg + G2_ALO + a_row * LDA + a_kb;
        const uint32_t bHi = stg + G2_BHI + b_row * LDA + b_kb;
        const uint32_t bLo = stg + G2_BLO + b_row * LDA + b_kb;

        #pragma unroll
        for (int kk = 0; kk < 2; ++kk) {
            const uint32_t koff = (uint32_t)kk * 32u;

            uint32_t ahi[4][4], alo[4][4];
            #pragma unroll
            for (int mt = 0; mt < 4; ++mt) {
                ldmatrix_x4(ahi[mt][0], ahi[mt][1], ahi[mt][2], ahi[mt][3],
                            aHi + (uint32_t)mt * 16u * LDA + koff);
                ldmatrix_x4(alo[mt][0], alo[mt][1], alo[mt][2], alo[mt][3],
                            aLo + (uint32_t)mt * 16u * LDA + koff);
            }
            uint32_t bhi[4][2], blo[4][2];
            #pragma unroll
            for (int ntp = 0; ntp < 2; ++ntp) {
                uint32_t r0, r1, r2, r3;
                ldmatrix_x4(r0, r1, r2, r3, bHi + (uint32_t)ntp * 16u * LDA + koff);
                bhi[ntp * 2][0] = r0; bhi[ntp * 2][1] = r1;
                bhi[ntp * 2 + 1][0] = r2; bhi[ntp * 2 + 1][1] = r3;
                ldmatrix_x4(r0, r1, r2, r3, bLo + (uint32_t)ntp * 16u * LDA + koff);
                blo[ntp * 2][0] = r0; blo[ntp * 2][1] = r1;
                blo[ntp * 2 + 1][0] = r2; blo[ntp * 2 + 1][1] = r3;
            }

            #pragma unroll
            for (int mt = 0; mt < 4; ++mt)
                #pragma unroll
                for (int nt = 0; nt < 4; ++nt) {
                    mma_bf16(acc[mt][nt], ahi[mt][0], ahi[mt][1], ahi[mt][2], ahi[mt][3],
                             bhi[nt][0], bhi[nt][1]);
                    mma_bf16(acc[mt][nt], ahi[mt][0], ahi[mt][1], ahi[mt][2], ahi[mt][3],
                             blo[nt][0], blo[nt][1]);
                    mma_bf16(acc[mt][nt], alo[mt][0], alo[mt][1], alo[mt][2], alo[mt][3],
                             bhi[nt][0], bhi[nt][1]);
                }
        }
    }

    const int g  = lane >> 2;
    const int tg = lane & 3;
    #pragma unroll
    for (int mt = 0; mt < 4; ++mt)
        #pragma unroll
        for (int nt = 0; nt < 4; ++nt) {
            int n    = wn * 32 + nt * 8 + tg * 2;   // 0..127
            int gsel = n >> 6;
            int c64  = n & 63;
            const float* bp = bias + (size_t)(grp0 + gsel) * 64;
            float b0 = bp[c64], b1 = bp[c64 + 1];
            float* Cp = C + (size_t)(grp0 + gsel) * gStrideC;
            int r0 = m0 + wm * 64 + mt * 16 + g;
            float2 o0 = make_float2(acc[mt][nt][0] + b0, acc[mt][nt][1] + b1);
            float2 o1 = make_float2(acc[mt][nt][2] + b0, acc[mt][nt][3] + b1);
            *(float2*)(Cp + (size_t)r0 * ldC + c64)       = o0;
            *(float2*)(Cp + (size_t)(r0 + 8) * ldC + c64) = o1;
        }
}

// ============================================================================
// attn_mma: tensor-core flash attention, 3-stage cp.async, 1 sync per chunk.
//   2 CTAs/SM via launch bounds (regs capped 128). Epilogue emits split av.
// ============================================================================
#define LDS_ROW 144u
#define ST_KHI 0u
#define ST_KLO 9216u
#define ST_VHI 18432u
#define ST_VLO 27648u
#define STAGE_BYTES 36864u
#define ATTN_SMEM (3 * 36864)

__global__ __launch_bounds__(256, 2)
void attn_mma()
{
    extern __shared__ __align__(128) char smem[];
    const uint32_t sb = smem_u32(smem);
    const int tid  = threadIdx.x;
    const int lane = tid & 31;
    const int wid  = tid >> 5;
    const int g    = lane >> 2;
    const int tg   = lane & 3;
    const int hb   = blockIdx.y;
    const int hd   = hb >> 2;
    const int b    = hb & 3;
    const int q0   = blockIdx.x * 128;

    const float* Qg = g_ctx + ((size_t)hd * 8192 + b * 2048 + q0) * 64;
    const __nv_bfloat16* Khi = g_khi  + (size_t)hb * 2048 * 64;
    const __nv_bfloat16* Klo = g_klo  + (size_t)hb * 2048 * 64;
    const __nv_bfloat16* Vhi = g_vthi + (size_t)hb * 64 * 2048;
    const __nv_bfloat16* Vlo = g_vtlo + (size_t)hb * 64 * 2048;

    // ---- stage Q (scaled by 8*log2e), split, extract fragments ----
    const float QSCALE = 11.5415603272f;   // 8 / ln(2)
    #pragma unroll
    for (int i = 0; i < 8; ++i) {
        int idx = tid + i * 256;
        int row = idx >> 4;
        int c4  = idx & 15;
        float4 v = *(const float4*)(Qg + (size_t)row * 64 + c4 * 4);
        v.x *= QSCALE; v.y *= QSCALE; v.z *= QSCALE; v.w *= QSCALE;
        uint32_t h01, h23, l01, l23;
        split4(v, h01, h23, l01, l23);
        uint32_t off = (uint32_t)row * LDS_ROW + (uint32_t)c4 * 8u;
        *(uint2*)(smem + off)         = make_uint2(h01, h23);
        *(uint2*)(smem + 18432 + off) = make_uint2(l01, l23);
    }
    __syncthreads();

    uint32_t qhi[4][4], qlo[4][4];
    {
        const uint32_t qrow = (uint32_t)(wid * 16 + (lane & 7) + ((lane >> 3) & 1) * 8);
        const uint32_t kb   = (uint32_t)(lane >> 4) * 16u;
        const uint32_t aH = sb + qrow * LDS_ROW + kb;
        const uint32_t aL = sb + 18432 + qrow * LDS_ROW + kb;
        #pragma unroll
        for (int t = 0; t < 4; ++t) {
            ldmatrix_x4(qhi[t][0], qhi[t][1], qhi[t][2], qhi[t][3], aH + t * 32u);
            ldmatrix_x4(qlo[t][0], qlo[t][1], qlo[t][2], qlo[t][3], aL + t * 32u);
        }
    }
    __syncthreads();   // Q consumed — smem free for stages

    float mA = -1e30f, mB = -1e30f, lA = 0.f, lB = 0.f;
    float oacc[8][4];
    #pragma unroll
    for (int j = 0; j < 8; ++j)
        #pragma unroll
        for (int i = 0; i < 4; ++i) oacc[j][i] = 0.f;

    const uint32_t brow = (uint32_t)((lane & 7) + (lane >> 4) * 8);
    const uint32_t bkb  = (uint32_t)((lane >> 3) & 1) * 16u;

    const int cp_row = tid >> 3;     // 0..31
    const int cp_c   = tid & 7;      // 16B granule
    auto issue = [&](int j0, uint32_t stg) {
        #pragma unroll
        for (int i = 0; i < 2; ++i) {
            int row = cp_row + i * 32;
            uint32_t doff = stg + (uint32_t)row * LDS_ROW + (uint32_t)cp_c * 16u;
            cp_async16(doff + ST_KHI, Khi + ((size_t)(j0 + row)) * 64 + cp_c * 8);
            cp_async16(doff + ST_KLO, Klo + ((size_t)(j0 + row)) * 64 + cp_c * 8);
            cp_async16(doff + ST_VHI, Vhi + ((size_t)row) * 2048 + j0 + cp_c * 8);
            cp_async16(doff + ST_VLO, Vlo + ((size_t)row) * 2048 + j0 + cp_c * 8);
        }
        cp_commit();
    };

    issue(0, sb);
    issue(64, sb + STAGE_BYTES);

    for (int j = 0; j < 32; ++j) {
        if (j < 31) cp_wait<1>(); else cp_wait<0>();
        __syncthreads();
        if (j + 2 < 32) issue((j + 2) * 64, sb + (uint32_t)((j + 2) % 3) * STAGE_BYTES);

        const uint32_t stg = sb + (uint32_t)(j % 3) * STAGE_BYTES;

        // ---- S = Qscaled @ K^T (split 3-term), log2 units ----
        float sacc[8][4];
        #pragma unroll
        for (int jj = 0; jj < 8; ++jj)
            #pragma unroll
            for (int i = 0; i < 4; ++i) sacc[jj][i] = 0.f;

        #pragma unroll
        for (int td = 0; td < 4; ++td) {
            uint32_t bhi[8][2], blo[8][2];
            #pragma unroll
            for (int ntp = 0; ntp < 4; ++ntp) {
                uint32_t base = (uint32_t)(ntp * 16) * LDS_ROW + brow * LDS_ROW + bkb
                                + (uint32_t)td * 32u;
                uint32_t r0, r1, r2, r3;
                ldmatrix_x4(r0, r1, r2, r3, stg + ST_KHI + base);
                bhi[ntp * 2][0] = r0; bhi[ntp * 2][1] = r1;
                bhi[ntp * 2 + 1][0] = r2; bhi[ntp * 2 + 1][1] = r3;
                ldmatrix_x4(r0, r1, r2, r3, stg + ST_KLO + base);
                blo[ntp * 2][0] = r0; blo[ntp * 2][1] = r1;
                blo[ntp * 2 + 1][0] = r2; blo[ntp * 2 + 1][1] = r3;
            }
            #pragma unroll
            for (int nt = 0; nt < 8; ++nt) {
                mma_bf16(sacc[nt], qhi[td][0], qhi[td][1], qhi[td][2], qhi[td][3],
                         bhi[nt][0], bhi[nt][1]);
                mma_bf16(sacc[nt], qhi[td][0], qhi[td][1], qhi[td][2], qhi[td][3],
                         blo[nt][0], blo[nt][1]);
                mma_bf16(sacc[nt], qlo[td][0], qlo[td][1], qlo[td][2], qlo[td][3],
                         bhi[nt][0], bhi[nt][1]);
            }
        }

        // ---- online softmax (log2 domain) ----
        float rmA = -1e30f, rmB = -1e30f;
        #pragma unroll
        for (int jj = 0; jj < 8; ++jj) {
            rmA = fmaxf(rmA, fmaxf(sacc[jj][0], sacc[jj][1]));
            rmB = fmaxf(rmB, fmaxf(sacc[jj][2], sacc[jj][3]));
        }
        rmA = fmaxf(rmA, __shfl_xor_sync(0xffffffffu, rmA, 1));
        rmA = fmaxf(rmA, __shfl_xor_sync(0xffffffffu, rmA, 2));
        rmB = fmaxf(rmB, __shfl_xor_sync(0xffffffffu, rmB, 1));
        rmB = fmaxf(rmB, __shfl_xor_sync(0xffffffffu, rmB, 2));

        float mnA = fmaxf(mA, rmA), mnB = fmaxf(mB, rmB);
        float corrA = exp2_fast(mA - mnA), corrB = exp2_fast(mB - mnB);

        float sumA = 0.f, sumB = 0.f;
        uint32_t phi[4][4], plo[4][4];
        #pragma unroll
        for (int jj = 0; jj < 8; ++jj) {
            float p0 = exp2_fast(sacc[jj][0] - mnA);
            float p1 = exp2_fast(sacc[jj][1] - mnA);
            float p2 = exp2_fast(sacc[jj][2] - mnB);
            float p3 = exp2_fast(sacc[jj][3] - mnB);
            sumA += p0 + p1; sumB += p2 + p3;
            int t = jj >> 1;
            int o = (jj & 1) * 2;
            uint32_t h01 = pack_bf16x2(p0, p1);
            uint32_t h23 = pack_bf16x2(p2, p3);
            phi[t][o]     = h01;
            phi[t][o + 1] = h23;
            float r0 = p0 - __int_as_float(h01 << 16);
            float r1 = p1 - __int_as_float(h01 & 0xFFFF0000u);
            float r2 = p2 - __int_as_float(h23 << 16);
            float r3 = p3 - __int_as_float(h23 & 0xFFFF0000u);
            plo[t][o]     = pack_bf16x2(r0, r1);
            plo[t][o + 1] = pack_bf16x2(r2, r3);
        }
        sumA += __shfl_xor_sync(0xffffffffu, sumA, 1);
        sumA += __shfl_xor_sync(0xffffffffu, sumA, 2);
        sumB += __shfl_xor_sync(0xffffffffu, sumB, 1);
        sumB += __shfl_xor_sync(0xffffffffu, sumB, 2);

        lA = lA * corrA + sumA;
        lB = lB * corrB + sumB;
        mA = mnA; mB = mnB;

        #pragma unroll
        for (int jj = 0; jj < 8; ++jj) {
            oacc[jj][0] *= corrA; oacc[jj][1] *= corrA;
            oacc[jj][2] *= corrB; oacc[jj][3] *= corrB;
        }

        // ---- O += P @ V (split 3-term) ----
        #pragma unroll
        for (int t = 0; t < 4; ++t) {
            uint32_t vhi[8][2], vlo[8][2];
            #pragma unroll
            for (int ntp = 0; ntp < 4; ++ntp) {
                uint32_t base = (uint32_t)(ntp * 16) * LDS_ROW + brow * LDS_ROW + bkb
                                + (uint32_t)t * 32u;
                uint32_t r0, r1, r2, r3;
                ldmatrix_x4(r0, r1, r2, r3, stg + ST_VHI + base);
                vhi[ntp * 2][0] = r0; vhi[ntp * 2][1] = r1;
                vhi[ntp * 2 + 1][0] = r2; vhi[ntp * 2 + 1][1] = r3;
                ldmatrix_x4(r0, r1, r2, r3, stg + ST_VLO + base);
                vlo[ntp * 2][0] = r0; vlo[ntp * 2][1] = r1;
                vlo[ntp * 2 + 1][0] = r2; vlo[ntp * 2 + 1][1] = r3;
            }
            #pragma unroll
            for (int nd = 0; nd < 8; ++nd) {
                mma_bf16(oacc[nd], phi[t][0], phi[t][1], phi[t][2], phi[t][3],
                         vhi[nd][0], vhi[nd][1]);
                mma_bf16(oacc[nd], phi[t][0], phi[t][1], phi[t][2], phi[t][3],
                         vlo[nd][0], vlo[nd][1]);
                mma_bf16(oacc[nd], plo[t][0], plo[t][1], plo[t][2], plo[t][3],
                         vhi[nd][0], vhi[nd][1]);
            }
        }
    }

    // ---- epilogue: normalize, split to bf16 hi/lo, write g_avhi/g_avlo ----
    const float invA = 1.f / lA, invB = 1.f / lB;
    const int rowA = q0 + wid * 16 + g;
    const int rowB = rowA + 8;
    #pragma unroll
    for (int jd = 0; jd < 8; ++jd) {
        int col = hd * 64 + jd * 8 + tg * 2;
        {
            float o0 = oacc[jd][0] * invA, o1 = oacc[jd][1] * invA;
            uint32_t h = pack_bf16x2(o0, o1);
            float r0 = o0 - __int_as_float(h << 16);
            float r1 = o1 - __int_as_float(h & 0xFFFF0000u);
            uint32_t l = pack_bf16x2(r0, r1);
            size_t base = (size_t)(b * 2048 + rowA) * 1024 + col;
            *(uint32_t*)&g_avhi[base] = h;
            *(uint32_t*)&g_avlo[base] = l;
        }
        {
            float o2 = oacc[jd][2] * invB, o3 = oacc[jd][3] * invB;
            uint32_t h = pack_bf16x2(o2, o3);
            float r2 = o2 - __int_as_float(h << 16);
            float r3 = o3 - __int_as_float(h & 0xFFFF0000u);
            uint32_t l = pack_bf16x2(r2, r3);
            size_t base = (size_t)(b * 2048 + rowB) * 1024 + col;
            *(uint32_t*)&g_avhi[base] = h;
            *(uint32_t*)&g_avlo[base] = l;
        }
    }
}

// ============================================================================
extern "C" void kernel_launch(void* const* d_in, const int* in_sizes, int n_in,
                              void* d_out, int out_size)
{
    const float* x    = (const float*)d_in[0];   // (4, 2048, 1024)
    const float* Wqkv = (const float*)d_in[1];   // (48, 1024, 64)
    const float* bqkv = (const float*)d_in[2];   // (48, 64)
    const float* Wp   = (const float*)d_in[3];   // (1024, 1024)
    const float* bp   = (const float*)d_in[4];   // (1024,)
    float* out = (float*)d_out;                  // (4, 2048, 1024)

    float* g_ctx_p;  cudaGetSymbolAddress((void**)&g_ctx_p, g_ctx);
    __nv_bfloat16 *xhi, *xlo, *wthi, *wtlo, *wphi, *wplo, *avhi, *avlo;
    cudaGetSymbolAddress((void**)&xhi,  g_xhi);
    cudaGetSymbolAddress((void**)&xlo,  g_xlo);
    cudaGetSymbolAddress((void**)&wthi, g_wthi);
    cudaGetSymbolAddress((void**)&wtlo, g_wtlo);
    cudaGetSymbolAddress((void**)&wphi, g_wphi);
    cudaGetSymbolAddress((void**)&wplo, g_wplo);
    cudaGetSymbolAddress((void**)&avhi, g_avhi);
    cudaGetSymbolAddress((void**)&avlo, g_avlo);

    cudaFuncSetAttribute(gemm_bf2, cudaFuncAttributeMaxDynamicSharedMemorySize,
                         GEMM_SMEM);
    cudaFuncSetAttribute(attn_mma, cudaFuncAttributeMaxDynamicSharedMemorySize,
                         ATTN_SMEM);

    // 1) preps: split x, Wp; transpose+split Wqkv
    prep_x<<<2048, 256>>>(x);
    split_wp<<<256, 256>>>(Wp);
    transpose_w<<<dim3(32, 2, 48), dim3(32, 8)>>>(Wqkv);

    // 2) QKV: ctx[e] = x @ Wqkv[e]^T + bqkv[e]   (2 ensembles per CTA)
    gemm_bf2<<<dim3(64, 24), 256, GEMM_SMEM>>>(xhi, xlo, wthi, wtlo, bqkv, g_ctx_p,
                                               /*ldC=*/64,
                                               /*gStrideC=*/(size_t)8192 * 64);

    // 2.5) pre-split K/V (V transposed)
    prep_kv<<<dim3(32, 64), 256>>>();

    // 3) attention (3-stage cp.async, 2 CTAs/SM)
    attn_mma<<<dim3(16, 64), 256, ATTN_SMEM>>>();

    // 4) proj: out = av @ Wp^T + bp   (2 col-groups per CTA)
    gemm_bf2<<<dim3(64, 8), 256, GEMM_SMEM>>>(avhi, avlo, wphi, wplo, bp, out,
                                              /*ldC=*/1024, /*gStrideC=*/64);
}

// round 10
// speedup vs baseline: 1.2770x; 1.2594x over previous
#include <cuda_runtime.h>
#include <cuda_bf16.h>
#include <cuda_fp16.h>
#include <stdint.h>
#include <math.h>

// ============================================================================
// Scratch (device globals — no allocations allowed).
// ============================================================================
__device__ float g_ctx[48ull * 8192ull * 64ull];   // [e][row][h], ~100.7 MB
__device__ __align__(16) __nv_bfloat16 g_xhi [8192ull * 1024];
__device__ __align__(16) __nv_bfloat16 g_xlo [8192ull * 1024];
__device__ __align__(16) __half        g_x16 [8192ull * 1024];      // fp16 x (V path)
__device__ __align__(16) __nv_bfloat16 g_wthi[48ull * 64 * 1024];   // Wqkv^T [e][h][d]
__device__ __align__(16) __nv_bfloat16 g_wtlo[48ull * 64 * 1024];
__device__ __align__(16) __half        g_wt16[16ull * 64 * 1024];   // V-ensemble W fp16
__device__ __align__(16) __nv_bfloat16 g_wphi[1024ull * 1024];      // Wp [n][k]
__device__ __align__(16) __nv_bfloat16 g_wplo[1024ull * 1024];
__device__ __align__(16) __nv_bfloat16 g_avhi[8192ull * 1024];
__device__ __align__(16) __nv_bfloat16 g_avlo[8192ull * 1024];
__device__ __align__(16) __nv_bfloat16 g_khi [16ull * 4 * 2048 * 64];   // [hb][l][d]
__device__ __align__(16) __nv_bfloat16 g_klo [16ull * 4 * 2048 * 64];
__device__ __align__(16) __half        g_vt16[16ull * 4 * 64 * 2048];   // [hb][d][l] fp16

// ============================================================================
// PTX helpers (sm_80-era ISA — compiles for plain compute_103)
// ============================================================================
__device__ __forceinline__ uint32_t smem_u32(const void* p) {
    uint32_t a;
    asm("{ .reg .u64 t; cvta.to.shared.u64 t, %1; cvt.u32.u64 %0, t; }"
        : "=r"(a) : "l"(p));
    return a;
}

__device__ __forceinline__ void ldmatrix_x4(uint32_t& r0, uint32_t& r1,
                                            uint32_t& r2, uint32_t& r3,
                                            uint32_t addr) {
    asm volatile("ldmatrix.sync.aligned.m8n8.x4.shared.b16 {%0,%1,%2,%3}, [%4];"
                 : "=r"(r0), "=r"(r1), "=r"(r2), "=r"(r3) : "r"(addr));
}

__device__ __forceinline__ void mma_bf16(float* c,
                                         uint32_t a0, uint32_t a1, uint32_t a2, uint32_t a3,
                                         uint32_t b0, uint32_t b1) {
    asm volatile("mma.sync.aligned.m16n8k16.row.col.f32.bf16.bf16.f32 "
                 "{%0,%1,%2,%3}, {%4,%5,%6,%7}, {%8,%9}, {%0,%1,%2,%3};"
                 : "+f"(c[0]), "+f"(c[1]), "+f"(c[2]), "+f"(c[3])
                 : "r"(a0), "r"(a1), "r"(a2), "r"(a3), "r"(b0), "r"(b1));
}

__device__ __forceinline__ void mma_f16(float* c,
                                        uint32_t a0, uint32_t a1, uint32_t a2, uint32_t a3,
                                        uint32_t b0, uint32_t b1) {
    asm volatile("mma.sync.aligned.m16n8k16.row.col.f32.f16.f16.f32 "
                 "{%0,%1,%2,%3}, {%4,%5,%6,%7}, {%8,%9}, {%0,%1,%2,%3};"
                 : "+f"(c[0]), "+f"(c[1]), "+f"(c[2]), "+f"(c[3])
                 : "r"(a0), "r"(a1), "r"(a2), "r"(a3), "r"(b0), "r"(b1));
}

__device__ __forceinline__ void cp_async16(uint32_t dst, const void* src) {
    asm volatile("cp.async.cg.shared.global [%0], [%1], 16;"
                 :: "r"(dst), "l"(src) : "memory");
}
__device__ __forceinline__ void cp_commit() {
    asm volatile("cp.async.commit_group;" ::: "memory");
}
template <int N>
__device__ __forceinline__ void cp_wait() {
    asm volatile("cp.async.wait_group %0;" :: "n"(N) : "memory");
}

__device__ __forceinline__ uint32_t pack_bf16x2(float x, float y) {
    uint32_t r;
    asm("cvt.rn.bf16x2.f32 %0, %1, %2;" : "=r"(r) : "f"(y), "f"(x));
    return r;
}
__device__ __forceinline__ uint32_t pack_f16x2(float x, float y) {
    uint32_t r;
    asm("cvt.rn.f16x2.f32 %0, %1, %2;" : "=r"(r) : "f"(y), "f"(x));
    return r;
}

// fast 2^t for t <= 0, FFMA/ALU only (no MUFU). rel err ~2.5e-6.
__device__ __forceinline__ float exp2_fast(float t) {
    float r = fmaxf(t, -30.f);
    float z = r + 12582912.f;
    int   i = __float_as_int(z);
    float f = r - (z - 12582912.f);
    float p = 1.33335581e-3f;
    p = fmaf(p, f, 9.61812911e-3f);
    p = fmaf(p, f, 5.55041087e-2f);
    p = fmaf(p, f, 2.40226507e-1f);
    p = fmaf(p, f, 6.93147181e-1f);
    p = fmaf(p, f, 1.0f);
    return p * __int_as_float((i + 127) << 23);
}

__device__ __forceinline__ void split4(float4 v, uint32_t& h01, uint32_t& h23,
                                       uint32_t& l01, uint32_t& l23) {
    h01 = pack_bf16x2(v.x, v.y);
    h23 = pack_bf16x2(v.z, v.w);
    float r0 = v.x - __int_as_float(h01 << 16);
    float r1 = v.y - __int_as_float(h01 & 0xFFFF0000u);
    float r2 = v.z - __int_as_float(h23 << 16);
    float r3 = v.w - __int_as_float(h23 & 0xFFFF0000u);
    l01 = pack_bf16x2(r0, r1);
    l23 = pack_bf16x2(r2, r3);
}

// ============================================================================
// Prep kernels
// ============================================================================
__global__ __launch_bounds__(256) void prep_x(const float* __restrict__ x) {
    #pragma unroll
    for (int i = 0; i < 4; ++i) {
        size_t idx = (size_t)blockIdx.x * 256 + threadIdx.x + (size_t)i * 524288;
        float4 v = *(const float4*)(x + idx * 4);
        uint32_t h01, h23, l01, l23;
        split4(v, h01, h23, l01, l23);
        *(uint2*)&g_xhi[idx * 4] = make_uint2(h01, h23);
        *(uint2*)&g_xlo[idx * 4] = make_uint2(l01, l23);
        *(uint2*)&g_x16[idx * 4] = make_uint2(pack_f16x2(v.x, v.y),
                                              pack_f16x2(v.z, v.w));
    }
}

__global__ __launch_bounds__(256) void split_wp(const float* __restrict__ Wp) {
    #pragma unroll
    for (int i = 0; i < 4; ++i) {
        size_t idx = (size_t)blockIdx.x * 256 + threadIdx.x + (size_t)i * 65536;
        float4 v = *(const float4*)(Wp + idx * 4);
        uint32_t h01, h23, l01, l23;
        split4(v, h01, h23, l01, l23);
        *(uint2*)&g_wphi[idx * 4] = make_uint2(h01, h23);
        *(uint2*)&g_wplo[idx * 4] = make_uint2(l01, l23);
    }
}

__global__ void transpose_w(const float* __restrict__ W) {
    __shared__ float t[32][33];
    const int e  = blockIdx.z;
    const int k0 = blockIdx.x * 32;
    const int h0 = blockIdx.y * 32;
    const int tx = threadIdx.x, ty = threadIdx.y;
    #pragma unroll
    for (int i = 0; i < 32; i += 8)
        t[ty + i][tx] = W[(size_t)e * 65536 + (size_t)(k0 + ty + i) * 64 + h0 + tx];
    __syncthreads();
    #pragma unroll
    for (int i = 0; i < 32; i += 8) {
        float val = t[tx][ty + i];
        __nv_bfloat16 hi = __float2bfloat16(val);
        __nv_bfloat16 lo = __float2bfloat16(val - __bfloat162float(hi));
        size_t off = (size_t)e * 65536 + (size_t)(h0 + ty + i) * 1024 + k0 + tx;
        g_wthi[off] = hi;
        g_wtlo[off] = lo;
        if (e >= 32) {
            size_t o16 = (size_t)(e - 32) * 65536 + (size_t)(h0 + ty + i) * 1024 + k0 + tx;
            g_wt16[o16] = __float2half(val);
        }
    }
}

// prep K/V: K split bf16 hi/lo; V -> single fp16, transposed to [d][l].
__global__ __launch_bounds__(256)
void prep_kv()
{
    __shared__ __half vt16[64 * 72];

    const int tid = threadIdx.x;
    const int hb  = blockIdx.y;
    const int hd  = hb >> 2;
    const int b   = hb & 3;
    const int l0  = blockIdx.x * 64;

    const float* Kg = g_ctx + ((size_t)(16 + hd) * 8192 + (size_t)b * 2048 + l0) * 64;
    const float* Vg = g_ctx + ((size_t)(32 + hd) * 8192 + (size_t)b * 2048 + l0) * 64;

    #pragma unroll
    for (int i = 0; i < 4; ++i) {
        int idx = tid + i * 256;
        int row = idx >> 4;
        int c4  = idx & 15;
        float4 v = *(const float4*)(Kg + (size_t)row * 64 + c4 * 4);
        uint32_t h01, h23, l01, l23;
        split4(v, h01, h23, l01, l23);
        size_t off = ((size_t)hb * 2048 + l0 + row) * 64 + c4 * 4;
        *(uint2*)&g_khi[off] = make_uint2(h01, h23);
        *(uint2*)&g_klo[off] = make_uint2(l01, l23);
    }

    #pragma unroll
    for (int i = 0; i < 4; ++i) {
        int idx = tid + i * 256;
        int key = idx >> 4;
        int c4  = idx & 15;
        float4 v = *(const float4*)(Vg + (size_t)key * 64 + c4 * 4);
        int d = c4 * 4;
        vt16[(d + 0) * 72 + key] = __float2half(v.x);
        vt16[(d + 1) * 72 + key] = __float2half(v.y);
        vt16[(d + 2) * 72 + key] = __float2half(v.z);
        vt16[(d + 3) * 72 + key] = __float2half(v.w);
    }
    __syncthreads();

    #pragma unroll
    for (int i = 0; i < 2; ++i) {
        int idx = tid + i * 256;
        int d   = idx >> 3;
        int c   = idx & 7;
        uint4 hv = *(uint4*)&vt16[d * 72 + c * 8];
        size_t off = ((size_t)hb * 64 + d) * 2048 + l0 + c * 8;
        *(uint4*)&g_vt16[off] = hv;
    }
}

// ============================================================================
// gemm_bf2: 128x128 CTA (2 groups of 64 cols), warp 64x32 (2m x 4n),
//   pre-split bf16 3-term, 3-stage cp.async. Used for Q/K ensembles + proj.
// ============================================================================
#define LDA 80u
#define G2_AHI 0u
#define G2_ALO 10240u
#define G2_BHI 20480u
#define G2_BLO 30720u
#define G2_STG 40960u
#define GEMM_SMEM (3 * 40960)

__global__ __launch_bounds__(256)
void gemm_bf2(const __nv_bfloat16* __restrict__ Ahi, const __nv_bfloat16* __restrict__ Alo,
              const __nv_bfloat16* __restrict__ Bhi, const __nv_bfloat16* __restrict__ Blo,
              const float* __restrict__ bias, float* __restrict__ C,
              int ldC, size_t gStrideC)
{
    extern __shared__ __align__(128) char smem[];
    const uint32_t sb  = smem_u32(smem);
    const int tid  = threadIdx.x;
    const int lane = tid & 31;
    const int wid  = tid >> 5;
    const int wm   = wid & 1;
    const int wn   = wid >> 1;
    const int m0   = blockIdx.x * 128;
    const int grp0 = blockIdx.y * 2;

    const __nv_bfloat16* Bh0 = Bhi + (size_t)grp0 * 65536;
    const __nv_bfloat16* Bl0 = Blo + (size_t)grp0 * 65536;

    float acc[4][4][4];
    #pragma unroll
    for (int mt = 0; mt < 4; ++mt)
        #pragma unroll
        for (int nt = 0; nt < 4; ++nt)
            #pragma unroll
            for (int i = 0; i < 4; ++i) acc[mt][nt][i] = 0.f;

    const int cp_r = tid >> 2;
    const int cp_c = tid & 3;
    const int ce   = cp_c * 8;
    auto issue = [&](int ks, uint32_t stg) {
        const int k0 = ks * 32;
        uint32_t d0 = stg + (uint32_t)cp_r * LDA + (uint32_t)cp_c * 16u;
        uint32_t d1 = d0 + 64u * LDA;
        size_t a0 = (size_t)(m0 + cp_r) * 1024 + k0 + ce;
        size_t a1 = a0 + 64 * 1024;
        size_t b0 = (size_t)cp_r * 1024 + k0 + ce;
        cp_async16(d0 + G2_AHI, Ahi + a0);
        cp_async16(d1 + G2_AHI, Ahi + a1);
        cp_async16(d0 + G2_ALO, Alo + a0);
        cp_async16(d1 + G2_ALO, Alo + a1);
        cp_async16(d0 + G2_BHI, Bh0 + b0);
        cp_async16(d1 + G2_BHI, Bh0 + 65536 + b0);
        cp_async16(d0 + G2_BLO, Bl0 + b0);
        cp_async16(d1 + G2_BLO, Bl0 + 65536 + b0);
        cp_commit();
    };

    const uint32_t a_row = (uint32_t)(wm * 64 + (lane & 7) + ((lane >> 3) & 1) * 8);
    const uint32_t a_kb  = (uint32_t)(lane >> 4) * 16u;
    const uint32_t b_row = (uint32_t)(wn * 32 + (lane & 7) + (lane >> 4) * 8);
    const uint32_t b_kb  = (uint32_t)((lane >> 3) & 1) * 16u;

    issue(0, sb);
    issue(1, sb + G2_STG);

    for (int ks = 0; ks < 32; ++ks) {
        if (ks < 31) cp_wait<1>(); else cp_wait<0>();
        __syncthreads();
        if (ks + 2 < 32) issue(ks + 2, sb + (uint32_t)((ks + 2) % 3) * G2_STG);

        const uint32_t stg = sb + (uint32_t)(ks % 3) * G2_STG;
        const uint32_t aHi = stg + G2_AHI + a_row * LDA + a_kb;
        const uint32_t aLo = stg + G2_ALO + a_row * LDA + a_kb;
        const uint32_t bHi = stg + G2_BHI + b_row * LDA + b_kb;
        const uint32_t bLo = stg + G2_BLO + b_row * LDA + b_kb;

        #pragma unroll
        for (int kk = 0; kk < 2; ++kk) {
            const uint32_t koff = (uint32_t)kk * 32u;

            uint32_t ahi[4][4], alo[4][4];
            #pragma unroll
            for (int mt = 0; mt < 4; ++mt) {
                ldmatrix_x4(ahi[mt][0], ahi[mt][1], ahi[mt][2], ahi[mt][3],
                            aHi + (uint32_t)mt * 16u * LDA + koff);
                ldmatrix_x4(alo[mt][0], alo[mt][1], alo[mt][2], alo[mt][3],
                            aLo + (uint32_t)mt * 16u * LDA + koff);
            }
            uint32_t bhi[4][2], blo[4][2];
            #pragma unroll
            for (int ntp = 0; ntp < 2; ++ntp) {
                uint32_t r0, r1, r2, r3;
                ldmatrix_x4(r0, r1, r2, r3, bHi + (uint32_t)ntp * 16u * LDA + koff);
                bhi[ntp * 2][0] = r0; bhi[ntp * 2][1] = r1;
                bhi[ntp * 2 + 1][0] = r2; bhi[ntp * 2 + 1][1] = r3;
                ldmatrix_x4(r0, r1, r2, r3, bLo + (uint32_t)ntp * 16u * LDA + koff);
                blo[ntp * 2][0] = r0; blo[ntp * 2][1] = r1;
                blo[ntp * 2 + 1][0] = r2; blo[ntp * 2 + 1][1] = r3;
            }

            #pragma unroll
            for (int mt = 0; mt < 4; ++mt)
                #pragma unroll
                for (int nt = 0; nt < 4; ++nt) {
                    mma_bf16(acc[mt][nt], ahi[mt][0], ahi[mt][1], ahi[mt][2], ahi[mt][3],
                             bhi[nt][0], bhi[nt][1]);
                    mma_bf16(acc[mt][nt], ahi[mt][0], ahi[mt][1], ahi[mt][2], ahi[mt][3],
                             blo[nt][0], blo[nt][1]);
                    mma_bf16(acc[mt][nt], alo[mt][0], alo[mt][1], alo[mt][2], alo[mt][3],
                             bhi[nt][0], bhi[nt][1]);
                }
        }
    }

    const int g  = lane >> 2;
    const int tg = lane & 3;
    #pragma unroll
    for (int mt = 0; mt < 4; ++mt)
        #pragma unroll
        for (int nt = 0; nt < 4; ++nt) {
            int n    = wn * 32 + nt * 8 + tg * 2;
            int gsel = n >> 6;
            int c64  = n & 63;
            const float* bp = bias + (size_t)(grp0 + gsel) * 64;
            float b0 = bp[c64], b1 = bp[c64 + 1];
            float* Cp = C + (size_t)(grp0 + gsel) * gStrideC;
            int r0 = m0 + wm * 64 + mt * 16 + g;
            float2 o0 = make_float2(acc[mt][nt][0] + b0, acc[mt][nt][1] + b1);
            float2 o1 = make_float2(acc[mt][nt][2] + b0, acc[mt][nt][3] + b1);
            *(float2*)(Cp + (size_t)r0 * ldC + c64)       = o0;
            *(float2*)(Cp + (size_t)(r0 + 8) * ldC + c64) = o1;
        }
}

// ============================================================================
// gemm_f16: 1-term fp16 GEMM for V ensembles. 128x128 CTA, warp 64x32,
//   3-stage cp.async. 3x fewer MMAs than gemm_bf2.
// ============================================================================
#define GF_A 0u
#define GF_B 10240u
#define GF_STG 20480u
#define GF_SMEM (3 * 20480)

__global__ __launch_bounds__(256)
void gemm_f16(const __half* __restrict__ A, const __half* __restrict__ B,
              const float* __restrict__ bias, float* __restrict__ C,
              int ldC, size_t gStrideC)
{
    extern __shared__ __align__(128) char smem[];
    const uint32_t sb  = smem_u32(smem);
    const int tid  = threadIdx.x;
    const int lane = tid & 31;
    const int wid  = tid >> 5;
    const int wm   = wid & 1;
    const int wn   = wid >> 1;
    const int m0   = blockIdx.x * 128;
    const int grp0 = blockIdx.y * 2;

    const __half* B0 = B + (size_t)grp0 * 65536;

    float acc[4][4][4];
    #pragma unroll
    for (int mt = 0; mt < 4; ++mt)
        #pragma unroll
        for (int nt = 0; nt < 4; ++nt)
            #pragma unroll
            for (int i = 0; i < 4; ++i) acc[mt][nt][i] = 0.f;

    const int cp_r = tid >> 2;
    const int cp_c = tid & 3;
    const int ce   = cp_c * 8;
    auto issue = [&](int ks, uint32_t stg) {
        const int k0 = ks * 32;
        uint32_t d0 = stg + (uint32_t)cp_r * LDA + (uint32_t)cp_c * 16u;
        uint32_t d1 = d0 + 64u * LDA;
        size_t a0 = (size_t)(m0 + cp_r) * 1024 + k0 + ce;
        size_t a1 = a0 + 64 * 1024;
        size_t b0 = (size_t)cp_r * 1024 + k0 + ce;
        cp_async16(d0 + GF_A, A + a0);
        cp_async16(d1 + GF_A, A + a1);
        cp_async16(d0 + GF_B, B0 + b0);
        cp_async16(d1 + GF_B, B0 + 65536 + b0);
        cp_commit();
    };

    const uint32_t a_row = (uint32_t)(wm * 64 + (lane & 7) + ((lane >> 3) & 1) * 8);
    const uint32_t a_kb  = (uint32_t)(lane >> 4) * 16u;
    const uint32_t b_row = (uint32_t)(wn * 32 + (lane & 7) + (lane >> 4) * 8);
    const uint32_t b_kb  = (uint32_t)((lane >> 3) & 1) * 16u;

    issue(0, sb);
    issue(1, sb + GF_STG);

    for (int ks = 0; ks < 32; ++ks) {
        if (ks < 31) cp_wait<1>(); else cp_wait<0>();
        __syncthreads();
        if (ks + 2 < 32) issue(ks + 2, sb + (uint32_t)((ks + 2) % 3) * GF_STG);

        const uint32_t stg = sb + (uint32_t)(ks % 3) * GF_STG;
        const uint32_t aB = stg + GF_A + a_row * LDA + a_kb;
        const uint32_t bB = stg + GF_B + b_row * LDA + b_kb;

        #pragma unroll
        for (int kk = 0; kk < 2; ++kk) {
            const uint32_t koff = (uint32_t)kk * 32u;

            uint32_t af[4][4];
            #pragma unroll
            for (int mt = 0; mt < 4; ++mt)
                ldmatrix_x4(af[mt][0], af[mt][1], af[mt][2], af[mt][3],
                            aB + (uint32_t)mt * 16u * LDA + koff);
            uint32_t bf[4][2];
            #pragma unroll
            for (int ntp = 0; ntp < 2; ++ntp) {
                uint32_t r0, r1, r2, r3;
                ldmatrix_x4(r0, r1, r2, r3, bB + (uint32_t)ntp * 16u * LDA + koff);
                bf[ntp * 2][0] = r0; bf[ntp * 2][1] = r1;
                bf[ntp * 2 + 1][0] = r2; bf[ntp * 2 + 1][1] = r3;
            }

            #pragma unroll
            for (int mt = 0; mt < 4; ++mt)
                #pragma unroll
                for (int nt = 0; nt < 4; ++nt)
                    mma_f16(acc[mt][nt], af[mt][0], af[mt][1], af[mt][2], af[mt][3],
                            bf[nt][0], bf[nt][1]);
        }
    }

    const int g  = lane >> 2;
    const int tg = lane & 3;
    #pragma unroll
    for (int mt = 0; mt < 4; ++mt)
        #pragma unroll
        for (int nt = 0; nt < 4; ++nt) {
            int n    = wn * 32 + nt * 8 + tg * 2;
            int gsel = n >> 6;
            int c64  = n & 63;
            const float* bp = bias + (size_t)(grp0 + gsel) * 64;
            float b0 = bp[c64], b1 = bp[c64 + 1];
            float* Cp = C + (size_t)(grp0 + gsel) * gStrideC;
            int r0 = m0 + wm * 64 + mt * 16 + g;
            float2 o0 = make_float2(acc[mt][nt][0] + b0, acc[mt][nt][1] + b1);
            float2 o1 = make_float2(acc[mt][nt][2] + b0, acc[mt][nt][3] + b1);
            *(float2*)(Cp + (size_t)r0 * ldC + c64)       = o0;
            *(float2*)(Cp + (size_t)(r0 + 8) * ldC + c64) = o1;
        }
}

// ============================================================================
// attn_mma: flash attention. S = 3-term bf16 (precision-critical logits),
//   PV = 1-term fp16 (P and V both fp16). 3-stage cp.async, 2 CTAs/SM.
// Stage: KHI 0 (9216), KLO 9216 (9216), V16 18432 (9216) = 27648 B.
// ============================================================================
#define LDS_ROW 144u
#define ST_KHI 0u
#define ST_KLO 9216u
#define ST_V16 18432u
#define STAGE_BYTES 27648u
#define ATTN_SMEM (3 * 27648)

__global__ __launch_bounds__(256, 2)
void attn_mma()
{
    extern __shared__ __align__(128) char smem[];
    const uint32_t sb = smem_u32(smem);
    const int tid  = threadIdx.x;
    const int lane = tid & 31;
    const int wid  = tid >> 5;
    const int g    = lane >> 2;
    const int tg   = lane & 3;
    const int hb   = blockIdx.y;
    const int hd   = hb >> 2;
    const int b    = hb & 3;
    const int q0   = blockIdx.x * 128;

    const float* Qg = g_ctx + ((size_t)hd * 8192 + b * 2048 + q0) * 64;
    const __nv_bfloat16* Khi = g_khi  + (size_t)hb * 2048 * 64;
    const __nv_bfloat16* Klo = g_klo  + (size_t)hb * 2048 * 64;
    const __half*        V16 = g_vt16 + (size_t)hb * 64 * 2048;

    // ---- stage Q (scaled by 8*log2e), split, extract fragments ----
    const float QSCALE = 11.5415603272f;   // 8 / ln(2)
    #pragma unroll
    for (int i = 0; i < 8; ++i) {
        int idx = tid + i * 256;
        int row = idx >> 4;
        int c4  = idx & 15;
        float4 v = *(const float4*)(Qg + (size_t)row * 64 + c4 * 4);
        v.x *= QSCALE; v.y *= QSCALE; v.z *= QSCALE; v.w *= QSCALE;
        uint32_t h01, h23, l01, l23;
        split4(v, h01, h23, l01, l23);
        uint32_t off = (uint32_t)row * LDS_ROW + (uint32_t)c4 * 8u;
        *(uint2*)(smem + off)         = make_uint2(h01, h23);
        *(uint2*)(smem + 18432 + off) = make_uint2(l01, l23);
    }
    __syncthreads();

    uint32_t qhi[4][4], qlo[4][4];
    {
        const uint32_t qrow = (uint32_t)(wid * 16 + (lane & 7) + ((lane >> 3) & 1) * 8);
        const uint32_t kb   = (uint32_t)(lane >> 4) * 16u;
        const uint32_t aH = sb + qrow * LDS_ROW + kb;
        const uint32_t aL = sb + 18432 + qrow * LDS_ROW + kb;
        #pragma unroll
        for (int t = 0; t < 4; ++t) {
            ldmatrix_x4(qhi[t][0], qhi[t][1], qhi[t][2], qhi[t][3], aH + t * 32u);
            ldmatrix_x4(qlo[t][0], qlo[t][1], qlo[t][2], qlo[t][3], aL + t * 32u);
        }
    }
    __syncthreads();   // Q consumed — smem free for stages

    float mA = -1e30f, mB = -1e30f, lA = 0.f, lB = 0.f;
    float oacc[8][4];
    #pragma unroll
    for (int j = 0; j < 8; ++j)
        #pragma unroll
        for (int i = 0; i < 4; ++i) oacc[j][i] = 0.f;

    const uint32_t brow = (uint32_t)((lane & 7) + (lane >> 4) * 8);
    const uint32_t bkb  = (uint32_t)((lane >> 3) & 1) * 16u;

    const int cp_row = tid >> 3;     // 0..31
    const int cp_c   = tid & 7;      // 16B granule
    auto issue = [&](int j0, uint32_t stg) {
        #pragma unroll
        for (int i = 0; i < 2; ++i) {
            int row = cp_row + i * 32;
            uint32_t doff = stg + (uint32_t)row * LDS_ROW + (uint32_t)cp_c * 16u;
            cp_async16(doff + ST_KHI, Khi + ((size_t)(j0 + row)) * 64 + cp_c * 8);
            cp_async16(doff + ST_KLO, Klo + ((size_t)(j0 + row)) * 64 + cp_c * 8);
            cp_async16(doff + ST_V16, V16 + ((size_t)row) * 2048 + j0 + cp_c * 8);
        }
        cp_commit();
    };

    issue(0, sb);
    issue(64, sb + STAGE_BYTES);

    for (int j = 0; j < 32; ++j) {
        if (j < 31) cp_wait<1>(); else cp_wait<0>();
        __syncthreads();
        if (j + 2 < 32) issue((j + 2) * 64, sb + (uint32_t)((j + 2) % 3) * STAGE_BYTES);

        const uint32_t stg = sb + (uint32_t)(j % 3) * STAGE_BYTES;

        // ---- S = Qscaled @ K^T (split 3-term bf16), log2 units ----
        float sacc[8][4];
        #pragma unroll
        for (int jj = 0; jj < 8; ++jj)
            #pragma unroll
            for (int i = 0; i < 4; ++i) sacc[jj][i] = 0.f;

        #pragma unroll
        for (int td = 0; td < 4; ++td) {
            uint32_t bhi[8][2], blo[8][2];
            #pragma unroll
            for (int ntp = 0; ntp < 4; ++ntp) {
                uint32_t base = (uint32_t)(ntp * 16) * LDS_ROW + brow * LDS_ROW + bkb
                                + (uint32_t)td * 32u;
                uint32_t r0, r1, r2, r3;
                ldmatrix_x4(r0, r1, r2, r3, stg + ST_KHI + base);
                bhi[ntp * 2][0] = r0; bhi[ntp * 2][1] = r1;
                bhi[ntp * 2 + 1][0] = r2; bhi[ntp * 2 + 1][1] = r3;
                ldmatrix_x4(r0, r1, r2, r3, stg + ST_KLO + base);
                blo[ntp * 2][0] = r0; blo[ntp * 2][1] = r1;
                blo[ntp * 2 + 1][0] = r2; blo[ntp * 2 + 1][1] = r3;
            }
            #pragma unroll
            for (int nt = 0; nt < 8; ++nt) {
                mma_bf16(sacc[nt], qhi[td][0], qhi[td][1], qhi[td][2], qhi[td][3],
                         bhi[nt][0], bhi[nt][1]);
                mma_bf16(sacc[nt], qhi[td][0], qhi[td][1], qhi[td][2], qhi[td][3],
                         blo[nt][0], blo[nt][1]);
                mma_bf16(sacc[nt], qlo[td][0], qlo[td][1], qlo[td][2], qlo[td][3],
                         bhi[nt][0], bhi[nt][1]);
            }
        }

        // ---- online softmax (log2 domain) ----
        float rmA = -1e30f, rmB = -1e30f;
        #pragma unroll
        for (int jj = 0; jj < 8; ++jj) {
            rmA = fmaxf(rmA, fmaxf(sacc[jj][0], sacc[jj][1]));
            rmB = fmaxf(rmB, fmaxf(sacc[jj][2], sacc[jj][3]));
        }
        rmA = fmaxf(rmA, __shfl_xor_sync(0xffffffffu, rmA, 1));
        rmA = fmaxf(rmA, __shfl_xor_sync(0xffffffffu, rmA, 2));
        rmB = fmaxf(rmB, __shfl_xor_sync(0xffffffffu, rmB, 1));
        rmB = fmaxf(rmB, __shfl_xor_sync(0xffffffffu, rmB, 2));

        float mnA = fmaxf(mA, rmA), mnB = fmaxf(mB, rmB);
        float corrA = exp2_fast(mA - mnA), corrB = exp2_fast(mB - mnB);

        float sumA = 0.f, sumB = 0.f;
        uint32_t pf[4][4];        // P fragments, fp16
        #pragma unroll
        for (int jj = 0; jj < 8; ++jj) {
            float p0 = exp2_fast(sacc[jj][0] - mnA);
            float p1 = exp2_fast(sacc[jj][1] - mnA);
            float p2 = exp2_fast(sacc[jj][2] - mnB);
            float p3 = exp2_fast(sacc[jj][3] - mnB);
            sumA += p0 + p1; sumB += p2 + p3;
            int t = jj >> 1;
            int o = (jj & 1) * 2;
            pf[t][o]     = pack_f16x2(p0, p1);
            pf[t][o + 1] = pack_f16x2(p2, p3);
        }
        sumA += __shfl_xor_sync(0xffffffffu, sumA, 1);
        sumA += __shfl_xor_sync(0xffffffffu, sumA, 2);
        sumB += __shfl_xor_sync(0xffffffffu, sumB, 1);
        sumB += __shfl_xor_sync(0xffffffffu, sumB, 2);

        lA = lA * corrA + sumA;
        lB = lB * corrB + sumB;
        mA = mnA; mB = mnB;

        #pragma unroll
        for (int jj = 0; jj < 8; ++jj) {
            oacc[jj][0] *= corrA; oacc[jj][1] *= corrA;
            oacc[jj][2] *= corrB; oacc[jj][3] *= corrB;
        }

        // ---- O += P @ V (1-term fp16) ----
        #pragma unroll
        for (int t = 0; t < 4; ++t) {
            uint32_t vf[8][2];
            #pragma unroll
            for (int ntp = 0; ntp < 4; ++ntp) {
                uint32_t base = (uint32_t)(ntp * 16) * LDS_ROW + brow * LDS_ROW + bkb
                                + (uint32_t)t * 32u;
                uint32_t r0, r1, r2, r3;
                ldmatrix_x4(r0, r1, r2, r3, stg + ST_V16 + base);
                vf[ntp * 2][0] = r0; vf[ntp * 2][1] = r1;
                vf[ntp * 2 + 1][0] = r2; vf[ntp * 2 + 1][1] = r3;
            }
            #pragma unroll
            for (int nd = 0; nd < 8; ++nd)
                mma_f16(oacc[nd], pf[t][0], pf[t][1], pf[t][2], pf[t][3],
                        vf[nd][0], vf[nd][1]);
        }
    }

    // ---- epilogue: normalize, split to bf16 hi/lo, write g_avhi/g_avlo ----
    const float invA = 1.f / lA, invB = 1.f / lB;
    const int rowA = q0 + wid * 16 + g;
    const int rowB = rowA + 8;
    #pragma unroll
    for (int jd = 0; jd < 8; ++jd) {
        int col = hd * 64 + jd * 8 + tg * 2;
        {
            float o0 = oacc[jd][0] * invA, o1 = oacc[jd][1] * invA;
            uint32_t h = pack_bf16x2(o0, o1);
            float r0 = o0 - __int_as_float(h << 16);
            float r1 = o1 - __int_as_float(h & 0xFFFF0000u);
            uint32_t l = pack_bf16x2(r0, r1);
            size_t base = (size_t)(b * 2048 + rowA) * 1024 + col;
            *(uint32_t*)&g_avhi[base] = h;
            *(uint32_t*)&g_avlo[base] = l;
        }
        {
            float o2 = oacc[jd][2] * invB, o3 = oacc[jd][3] * invB;
            uint32_t h = pack_bf16x2(o2, o3);
            float r2 = o2 - __int_as_float(h << 16);
            float r3 = o3 - __int_as_float(h & 0xFFFF0000u);
            uint32_t l = pack_bf16x2(r2, r3);
            size_t base = (size_t)(b * 2048 + rowB) * 1024 + col;
            *(uint32_t*)&g_avhi[base] = h;
            *(uint32_t*)&g_avlo[base] = l;
        }
    }
}

// ============================================================================
extern "C" void kernel_launch(void* const* d_in, const int* in_sizes, int n_in,
                              void* d_out, int out_size)
{
    const float* x    = (const float*)d_in[0];   // (4, 2048, 1024)
    const float* Wqkv = (const float*)d_in[1];   // (48, 1024, 64)
    const float* bqkv = (const float*)d_in[2];   // (48, 64)
    const float* Wp   = (const float*)d_in[3];   // (1024, 1024)
    const float* bp   = (const float*)d_in[4];   // (1024,)
    float* out = (float*)d_out;                  // (4, 2048, 1024)

    float* g_ctx_p;  cudaGetSymbolAddress((void**)&g_ctx_p, g_ctx);
    __nv_bfloat16 *xhi, *xlo, *wthi, *wtlo, *wphi, *wplo, *avhi, *avlo;
    __half *x16, *wt16;
    cudaGetSymbolAddress((void**)&xhi,  g_xhi);
    cudaGetSymbolAddress((void**)&xlo,  g_xlo);
    cudaGetSymbolAddress((void**)&x16,  g_x16);
    cudaGetSymbolAddress((void**)&wthi, g_wthi);
    cudaGetSymbolAddress((void**)&wtlo, g_wtlo);
    cudaGetSymbolAddress((void**)&wt16, g_wt16);
    cudaGetSymbolAddress((void**)&wphi, g_wphi);
    cudaGetSymbolAddress((void**)&wplo, g_wplo);
    cudaGetSymbolAddress((void**)&avhi, g_avhi);
    cudaGetSymbolAddress((void**)&avlo, g_avlo);

    cudaFuncSetAttribute(gemm_bf2, cudaFuncAttributeMaxDynamicSharedMemorySize,
                         GEMM_SMEM);
    cudaFuncSetAttribute(gemm_f16, cudaFuncAttributeMaxDynamicSharedMemorySize,
                         GF_SMEM);
    cudaFuncSetAttribute(attn_mma, cudaFuncAttributeMaxDynamicSharedMemorySize,
                         ATTN_SMEM);

    // 1) preps
    prep_x<<<2048, 256>>>(x);
    split_wp<<<256, 256>>>(Wp);
    transpose_w<<<dim3(32, 2, 48), dim3(32, 8)>>>(Wqkv);

    // 2a) Q/K ensembles (32 groups): 3-term bf16
    gemm_bf2<<<dim3(64, 16), 256, GEMM_SMEM>>>(xhi, xlo, wthi, wtlo, bqkv, g_ctx_p,
                                               /*ldC=*/64,
                                               /*gStrideC=*/(size_t)8192 * 64);
    // 2b) V ensembles (16 groups): 1-term fp16
    gemm_f16<<<dim3(64, 8), 256, GF_SMEM>>>(x16, wt16, bqkv + 32 * 64,
                                            g_ctx_p + 32ull * 8192 * 64,
                                            /*ldC=*/64,
                                            /*gStrideC=*/(size_t)8192 * 64);

    // 2.5) K split bf16 + V transposed fp16
    prep_kv<<<dim3(32, 64), 256>>>();

    // 3) attention (S bf16 3-term, PV fp16 1-term)
    attn_mma<<<dim3(16, 64), 256, ATTN_SMEM>>>();

    // 4) proj: out = av @ Wp^T + bp   (3-term bf16, full precision hedge)
    gemm_bf2<<<dim3(64, 8), 256, GEMM_SMEM>>>(avhi, avlo, wphi, wplo, bp, out,
                                              /*ldC=*/1024, /*gStrideC=*/64);
}

// round 11
// speedup vs baseline: 1.3755x; 1.0771x over previous
#include <cuda_runtime.h>
#include <cuda_bf16.h>
#include <cuda_fp16.h>
#include <stdint.h>
#include <math.h>

// ============================================================================
// Scratch (device globals — no allocations allowed).
// ============================================================================
__device__ __align__(16) __nv_bfloat16 g_xhi [8192ull * 1024];
__device__ __align__(16) __nv_bfloat16 g_xlo [8192ull * 1024];
__device__ __align__(16) __half        g_x16 [8192ull * 1024];
__device__ __align__(16) __nv_bfloat16 g_wthi[32ull * 64 * 1024];   // Q/K W^T [e][h][d]
__device__ __align__(16) __nv_bfloat16 g_wtlo[32ull * 64 * 1024];
__device__ __align__(16) __half        g_wt16[16ull * 64 * 1024];   // V W^T fp16
__device__ __align__(16) __half        g_wp16[1024ull * 1024];      // Wp fp16
__device__ __align__(16) __half        g_avhi[8192ull * 1024];      // av split fp16
__device__ __align__(16) __half        g_avlo[8192ull * 1024];
__device__ __align__(16) __nv_bfloat16 g_qhi [16ull * 8192 * 64];   // [hd][row][d], scaled
__device__ __align__(16) __nv_bfloat16 g_qlo [16ull * 8192 * 64];
__device__ __align__(16) __nv_bfloat16 g_khi [16ull * 8192 * 64];
__device__ __align__(16) __nv_bfloat16 g_klo [16ull * 8192 * 64];
__device__ __align__(16) __half        g_v16 [16ull * 8192 * 64];   // [hd][row][d]
__device__ __align__(16) __half        g_vt16[64ull * 64 * 2048];   // [hb][d][l]

// ============================================================================
// PTX helpers (sm_80-era ISA — compiles for plain compute_103)
// ============================================================================
__device__ __forceinline__ uint32_t smem_u32(const void* p) {
    uint32_t a;
    asm("{ .reg .u64 t; cvta.to.shared.u64 t, %1; cvt.u32.u64 %0, t; }"
        : "=r"(a) : "l"(p));
    return a;
}

__device__ __forceinline__ void ldmatrix_x4(uint32_t& r0, uint32_t& r1,
                                            uint32_t& r2, uint32_t& r3,
                                            uint32_t addr) {
    asm volatile("ldmatrix.sync.aligned.m8n8.x4.shared.b16 {%0,%1,%2,%3}, [%4];"
                 : "=r"(r0), "=r"(r1), "=r"(r2), "=r"(r3) : "r"(addr));
}

__device__ __forceinline__ void mma_bf16(float* c,
                                         uint32_t a0, uint32_t a1, uint32_t a2, uint32_t a3,
                                         uint32_t b0, uint32_t b1) {
    asm volatile("mma.sync.aligned.m16n8k16.row.col.f32.bf16.bf16.f32 "
                 "{%0,%1,%2,%3}, {%4,%5,%6,%7}, {%8,%9}, {%0,%1,%2,%3};"
                 : "+f"(c[0]), "+f"(c[1]), "+f"(c[2]), "+f"(c[3])
                 : "r"(a0), "r"(a1), "r"(a2), "r"(a3), "r"(b0), "r"(b1));
}

__device__ __forceinline__ void mma_f16(float* c,
                                        uint32_t a0, uint32_t a1, uint32_t a2, uint32_t a3,
                                        uint32_t b0, uint32_t b1) {
    asm volatile("mma.sync.aligned.m16n8k16.row.col.f32.f16.f16.f32 "
                 "{%0,%1,%2,%3}, {%4,%5,%6,%7}, {%8,%9}, {%0,%1,%2,%3};"
                 : "+f"(c[0]), "+f"(c[1]), "+f"(c[2]), "+f"(c[3])
                 : "r"(a0), "r"(a1), "r"(a2), "r"(a3), "r"(b0), "r"(b1));
}

__device__ __forceinline__ void cp_async16(uint32_t dst, const void* src) {
    asm volatile("cp.async.cg.shared.global [%0], [%1], 16;"
                 :: "r"(dst), "l"(src) : "memory");
}
__device__ __forceinline__ void cp_commit() {
    asm volatile("cp.async.commit_group;" ::: "memory");
}
template <int N>
__device__ __forceinline__ void cp_wait() {
    asm volatile("cp.async.wait_group %0;" :: "n"(N) : "memory");
}

__device__ __forceinline__ uint32_t pack_bf16x2(float x, float y) {
    uint32_t r;
    asm("cvt.rn.bf16x2.f32 %0, %1, %2;" : "=r"(r) : "f"(y), "f"(x));
    return r;
}
__device__ __forceinline__ uint32_t pack_f16x2(float x, float y) {
    uint32_t r;
    asm("cvt.rn.f16x2.f32 %0, %1, %2;" : "=r"(r) : "f"(y), "f"(x));
    return r;
}

// fast 2^t for t <= 0, FFMA/ALU only (no MUFU). rel err ~2.5e-6.
__device__ __forceinline__ float exp2_fast(float t) {
    float r = fmaxf(t, -30.f);
    float z = r + 12582912.f;
    int   i = __float_as_int(z);
    float f = r - (z - 12582912.f);
    float p = 1.33335581e-3f;
    p = fmaf(p, f, 9.61812911e-3f);
    p = fmaf(p, f, 5.55041087e-2f);
    p = fmaf(p, f, 2.40226507e-1f);
    p = fmaf(p, f, 6.93147181e-1f);
    p = fmaf(p, f, 1.0f);
    return p * __int_as_float((i + 127) << 23);
}

__device__ __forceinline__ void split4(float4 v, uint32_t& h01, uint32_t& h23,
                                       uint32_t& l01, uint32_t& l23) {
    h01 = pack_bf16x2(v.x, v.y);
    h23 = pack_bf16x2(v.z, v.w);
    float r0 = v.x - __int_as_float(h01 << 16);
    float r1 = v.y - __int_as_float(h01 & 0xFFFF0000u);
    float r2 = v.z - __int_as_float(h23 << 16);
    float r3 = v.w - __int_as_float(h23 & 0xFFFF0000u);
    l01 = pack_bf16x2(r0, r1);
    l23 = pack_bf16x2(r2, r3);
}

__device__ __forceinline__ void split2_bf(float a, float b, uint32_t& h, uint32_t& l) {
    h = pack_bf16x2(a, b);
    float ra = a - __int_as_float(h << 16);
    float rb = b - __int_as_float(h & 0xFFFF0000u);
    l = pack_bf16x2(ra, rb);
}

__device__ __forceinline__ void split2_f16(float a, float b, uint32_t& h, uint32_t& l) {
    h = pack_f16x2(a, b);
    float ha = __half2float(__ushort_as_half((unsigned short)(h & 0xFFFFu)));
    float hb = __half2float(__ushort_as_half((unsigned short)(h >> 16)));
    l = pack_f16x2(a - ha, b - hb);
}

// ============================================================================
// Prep kernels
// ============================================================================
__global__ __launch_bounds__(256) void prep_x(const float* __restrict__ x) {
    #pragma unroll
    for (int i = 0; i < 4; ++i) {
        size_t idx = (size_t)blockIdx.x * 256 + threadIdx.x + (size_t)i * 524288;
        float4 v = *(const float4*)(x + idx * 4);
        uint32_t h01, h23, l01, l23;
        split4(v, h01, h23, l01, l23);
        *(uint2*)&g_xhi[idx * 4] = make_uint2(h01, h23);
        *(uint2*)&g_xlo[idx * 4] = make_uint2(l01, l23);
        *(uint2*)&g_x16[idx * 4] = make_uint2(pack_f16x2(v.x, v.y),
                                              pack_f16x2(v.z, v.w));
    }
}

__global__ __launch_bounds__(256) void prep_wp16(const float* __restrict__ Wp) {
    #pragma unroll
    for (int i = 0; i < 4; ++i) {
        size_t idx = (size_t)blockIdx.x * 256 + threadIdx.x + (size_t)i * 65536;
        float4 v = *(const float4*)(Wp + idx * 4);
        *(uint2*)&g_wp16[idx * 4] = make_uint2(pack_f16x2(v.x, v.y),
                                               pack_f16x2(v.z, v.w));
    }
}

// transpose Wqkv [48][1024][64] -> Q/K: split bf16 [e][64][1024]; V: fp16.
__global__ void transpose_w(const float* __restrict__ W) {
    __shared__ float t[32][33];
    const int e  = blockIdx.z;
    const int k0 = blockIdx.x * 32;
    const int h0 = blockIdx.y * 32;
    const int tx = threadIdx.x, ty = threadIdx.y;
    #pragma unroll
    for (int i = 0; i < 32; i += 8)
        t[ty + i][tx] = W[(size_t)e * 65536 + (size_t)(k0 + ty + i) * 64 + h0 + tx];
    __syncthreads();
    #pragma unroll
    for (int i = 0; i < 32; i += 8) {
        float val = t[tx][ty + i];
        if (e < 32) {
            __nv_bfloat16 hi = __float2bfloat16(val);
            __nv_bfloat16 lo = __float2bfloat16(val - __bfloat162float(hi));
            size_t off = (size_t)e * 65536 + (size_t)(h0 + ty + i) * 1024 + k0 + tx;
            g_wthi[off] = hi;
            g_wtlo[off] = lo;
        } else {
            size_t o16 = (size_t)(e - 32) * 65536 + (size_t)(h0 + ty + i) * 1024 + k0 + tx;
            g_wt16[o16] = __float2half(val);
        }
    }
}

// transpose V fp16 [hb][l][d] -> [hb][d][l]
__global__ __launch_bounds__(256)
void prep_vt()
{
    __shared__ __half t[64 * 72];
    const int tid = threadIdx.x;
    const int hb  = blockIdx.y;
    const int l0  = blockIdx.x * 64;

    const __half* src = g_v16 + ((size_t)hb * 2048 + l0) * 64;
    #pragma unroll
    for (int i = 0; i < 4; ++i) {
        int idx = tid + i * 256;           // < 1024: 64 l x 16 granules (4 halfs)
        int l   = idx >> 4;
        int c4  = idx & 15;
        uint2 v = *(const uint2*)(src + (size_t)l * 64 + c4 * 4);
        int d = c4 * 4;
        t[(d + 0) * 72 + l] = __ushort_as_half((unsigned short)(v.x & 0xFFFF));
        t[(d + 1) * 72 + l] = __ushort_as_half((unsigned short)(v.x >> 16));
        t[(d + 2) * 72 + l] = __ushort_as_half((unsigned short)(v.y & 0xFFFF));
        t[(d + 3) * 72 + l] = __ushort_as_half((unsigned short)(v.y >> 16));
    }
    __syncthreads();
    #pragma unroll
    for (int i = 0; i < 2; ++i) {
        int idx = tid + i * 256;           // < 512: 64 d x 8 granules of 16B
        int d   = idx >> 3;
        int c   = idx & 7;
        uint4 v = *(uint4*)&t[d * 72 + c * 8];
        *(uint4*)&g_vt16[((size_t)hb * 64 + d) * 2048 + l0 + c * 8] = v;
    }
}

// ============================================================================
// gemm_qk: 128x128 CTA, 3-term split bf16. Computes Q/K ensembles (e 0..31);
//   epilogue writes Q (scaled by 8/ln2) and K pre-split bf16 hi/lo.
// ============================================================================
#define LDA 80u
#define G2_AHI 0u
#define G2_ALO 10240u
#define G2_BHI 20480u
#define G2_BLO 30720u
#define G2_STG 40960u
#define GEMM_SMEM (3 * 40960)

__global__ __launch_bounds__(256)
void gemm_qk(const float* __restrict__ bias)
{
    extern __shared__ __align__(128) char smem[];
    const uint32_t sb  = smem_u32(smem);
    const int tid  = threadIdx.x;
    const int lane = tid & 31;
    const int wid  = tid >> 5;
    const int wm   = wid & 1;
    const int wn   = wid >> 1;
    const int m0   = blockIdx.x * 128;
    const int grp0 = blockIdx.y * 2;

    const __nv_bfloat16* Ahi = g_xhi;
    const __nv_bfloat16* Alo = g_xlo;
    const __nv_bfloat16* Bh0 = g_wthi + (size_t)grp0 * 65536;
    const __nv_bfloat16* Bl0 = g_wtlo + (size_t)grp0 * 65536;

    float acc[4][4][4];
    #pragma unroll
    for (int mt = 0; mt < 4; ++mt)
        #pragma unroll
        for (int nt = 0; nt < 4; ++nt)
            #pragma unroll
            for (int i = 0; i < 4; ++i) acc[mt][nt][i] = 0.f;

    const int cp_r = tid >> 2;
    const int cp_c = tid & 3;
    const int ce   = cp_c * 8;
    auto issue = [&](int ks, uint32_t stg) {
        const int k0 = ks * 32;
        uint32_t d0 = stg + (uint32_t)cp_r * LDA + (uint32_t)cp_c * 16u;
        uint32_t d1 = d0 + 64u * LDA;
        size_t a0 = (size_t)(m0 + cp_r) * 1024 + k0 + ce;
        size_t a1 = a0 + 64 * 1024;
        size_t b0 = (size_t)cp_r * 1024 + k0 + ce;
        cp_async16(d0 + G2_AHI, Ahi + a0);
        cp_async16(d1 + G2_AHI, Ahi + a1);
        cp_async16(d0 + G2_ALO, Alo + a0);
        cp_async16(d1 + G2_ALO, Alo + a1);
        cp_async16(d0 + G2_BHI, Bh0 + b0);
        cp_async16(d1 + G2_BHI, Bh0 + 65536 + b0);
        cp_async16(d0 + G2_BLO, Bl0 + b0);
        cp_async16(d1 + G2_BLO, Bl0 + 65536 + b0);
        cp_commit();
    };

    const uint32_t a_row = (uint32_t)(wm * 64 + (lane & 7) + ((lane >> 3) & 1) * 8);
    const uint32_t a_kb  = (uint32_t)(lane >> 4) * 16u;
    const uint32_t b_row = (uint32_t)(wn * 32 + (lane & 7) + (lane >> 4) * 8);
    const uint32_t b_kb  = (uint32_t)((lane >> 3) & 1) * 16u;

    issue(0, sb);
    issue(1, sb + G2_STG);

    for (int ks = 0; ks < 32; ++ks) {
        if (ks < 31) cp_wait<1>(); else cp_wait<0>();
        __syncthreads();
        if (ks + 2 < 32) issue(ks + 2, sb + (uint32_t)((ks + 2) % 3) * G2_STG);

        const uint32_t stg = sb + (uint32_t)(ks % 3) * G2_STG;
        const uint32_t aHi = stg + G2_AHI + a_row * LDA + a_kb;
        const uint32_t aLo = stg + G2_ALO + a_row * LDA + a_kb;
        const uint32_t bHi = stg + G2_BHI + b_row * LDA + b_kb;
        const uint32_t bLo = stg + G2_BLO + b_row * LDA + b_kb;

        #pragma unroll
        for (int kk = 0; kk < 2; ++kk) {
            const uint32_t koff = (uint32_t)kk * 32u;

            uint32_t ahi[4][4], alo[4][4];
            #pragma unroll
            for (int mt = 0; mt < 4; ++mt) {
                ldmatrix_x4(ahi[mt][0], ahi[mt][1], ahi[mt][2], ahi[mt][3],
                            aHi + (uint32_t)mt * 16u * LDA + koff);
                ldmatrix_x4(alo[mt][0], alo[mt][1], alo[mt][2], alo[mt][3],
                            aLo + (uint32_t)mt * 16u * LDA + koff);
            }
            uint32_t bhi[4][2], blo[4][2];
            #pragma unroll
            for (int ntp = 0; ntp < 2; ++ntp) {
                uint32_t r0, r1, r2, r3;
                ldmatrix_x4(r0, r1, r2, r3, bHi + (uint32_t)ntp * 16u * LDA + koff);
                bhi[ntp * 2][0] = r0; bhi[ntp * 2][1] = r1;
                bhi[ntp * 2 + 1][0] = r2; bhi[ntp * 2 + 1][1] = r3;
                ldmatrix_x4(r0, r1, r2, r3, bLo + (uint32_t)ntp * 16u * LDA + koff);
                blo[ntp * 2][0] = r0; blo[ntp * 2][1] = r1;
                blo[ntp * 2 + 1][0] = r2; blo[ntp * 2 + 1][1] = r3;
            }

            #pragma unroll
            for (int mt = 0; mt < 4; ++mt)
                #pragma unroll
                for (int nt = 0; nt < 4; ++nt) {
                    mma_bf16(acc[mt][nt], ahi[mt][0], ahi[mt][1], ahi[mt][2], ahi[mt][3],
                             bhi[nt][0], bhi[nt][1]);
                    mma_bf16(acc[mt][nt], ahi[mt][0], ahi[mt][1], ahi[mt][2], ahi[mt][3],
                             blo[nt][0], blo[nt][1]);
                    mma_bf16(acc[mt][nt], alo[mt][0], alo[mt][1], alo[mt][2], alo[mt][3],
                             bhi[nt][0], bhi[nt][1]);
                }
        }
    }

    // ---- epilogue: add bias; Q (e<16) scaled by 8/ln2; write pre-split bf16 ----
    const float QSCALE = 11.5415603272f;
    const int g  = lane >> 2;
    const int tg = lane & 3;
    #pragma unroll
    for (int mt = 0; mt < 4; ++mt)
        #pragma unroll
        for (int nt = 0; nt < 4; ++nt) {
            int n    = wn * 32 + nt * 8 + tg * 2;
            int gsel = n >> 6;
            int c64  = n & 63;
            int e    = grp0 + gsel;
            const float* bp = bias + (size_t)e * 64;
            float b0 = bp[c64], b1 = bp[c64 + 1];
            int r0 = m0 + wm * 64 + mt * 16 + g;
            float v00 = acc[mt][nt][0] + b0, v01 = acc[mt][nt][1] + b1;
            float v10 = acc[mt][nt][2] + b0, v11 = acc[mt][nt][3] + b1;
            bool isQ = (e < 16);
            float s = isQ ? QSCALE : 1.f;
            v00 *= s; v01 *= s; v10 *= s; v11 *= s;
            __nv_bfloat16* dh = isQ ? g_qhi : g_khi;
            __nv_bfloat16* dl = isQ ? g_qlo : g_klo;
            int eo = isQ ? e : (e - 16);
            size_t base0 = ((size_t)eo * 8192 + r0) * 64 + c64;
            size_t base1 = base0 + 8 * 64;
            uint32_t h, l;
            split2_bf(v00, v01, h, l);
            *(uint32_t*)&dh[base0] = h;
            *(uint32_t*)&dl[base0] = l;
            split2_bf(v10, v11, h, l);
            *(uint32_t*)&dh[base1] = h;
            *(uint32_t*)&dl[base1] = l;
        }
}

// ============================================================================
// gemm_v16: 1-term fp16 GEMM for V ensembles; writes fp16 g_v16 [hd][row][d].
// ============================================================================
#define GF_A 0u
#define GF_B 10240u
#define GF_STG 20480u
#define GF_SMEM (3 * 20480)

__global__ __launch_bounds__(256)
void gemm_v16(const float* __restrict__ bias)
{
    extern __shared__ __align__(128) char smem[];
    const uint32_t sb  = smem_u32(smem);
    const int tid  = threadIdx.x;
    const int lane = tid & 31;
    const int wid  = tid >> 5;
    const int wm   = wid & 1;
    const int wn   = wid >> 1;
    const int m0   = blockIdx.x * 128;
    const int grp0 = blockIdx.y * 2;

    const __half* A  = g_x16;
    const __half* B0 = g_wt16 + (size_t)grp0 * 65536;

    float acc[4][4][4];
    #pragma unroll
    for (int mt = 0; mt < 4; ++mt)
        #pragma unroll
        for (int nt = 0; nt < 4; ++nt)
            #pragma unroll
            for (int i = 0; i < 4; ++i) acc[mt][nt][i] = 0.f;

    const int cp_r = tid >> 2;
    const int cp_c = tid & 3;
    const int ce   = cp_c * 8;
    auto issue = [&](int ks, uint32_t stg) {
        const int k0 = ks * 32;
        uint32_t d0 = stg + (uint32_t)cp_r * LDA + (uint32_t)cp_c * 16u;
        uint32_t d1 = d0 + 64u * LDA;
        size_t a0 = (size_t)(m0 + cp_r) * 1024 + k0 + ce;
        size_t a1 = a0 + 64 * 1024;
        size_t b0 = (size_t)cp_r * 1024 + k0 + ce;
        cp_async16(d0 + GF_A, A + a0);
        cp_async16(d1 + GF_A, A + a1);
        cp_async16(d0 + GF_B, B0 + b0);
        cp_async16(d1 + GF_B, B0 + 65536 + b0);
        cp_commit();
    };

    const uint32_t a_row = (uint32_t)(wm * 64 + (lane & 7) + ((lane >> 3) & 1) * 8);
    const uint32_t a_kb  = (uint32_t)(lane >> 4) * 16u;
    const uint32_t b_row = (uint32_t)(wn * 32 + (lane & 7) + (lane >> 4) * 8);
    const uint32_t b_kb  = (uint32_t)((lane >> 3) & 1) * 16u;

    issue(0, sb);
    issue(1, sb + GF_STG);

    for (int ks = 0; ks < 32; ++ks) {
        if (ks < 31) cp_wait<1>(); else cp_wait<0>();
        __syncthreads();
        if (ks + 2 < 32) issue(ks + 2, sb + (uint32_t)((ks + 2) % 3) * GF_STG);

        const uint32_t stg = sb + (uint32_t)(ks % 3) * GF_STG;
        const uint32_t aB = stg + GF_A + a_row * LDA + a_kb;
        const uint32_t bB = stg + GF_B + b_row * LDA + b_kb;

        #pragma unroll
        for (int kk = 0; kk < 2; ++kk) {
            const uint32_t koff = (uint32_t)kk * 32u;

            uint32_t af[4][4];
            #pragma unroll
            for (int mt = 0; mt < 4; ++mt)
                ldmatrix_x4(af[mt][0], af[mt][1], af[mt][2], af[mt][3],
                            aB + (uint32_t)mt * 16u * LDA + koff);
            uint32_t bf[4][2];
            #pragma unroll
            for (int ntp = 0; ntp < 2; ++ntp) {
                uint32_t r0, r1, r2, r3;
                ldmatrix_x4(r0, r1, r2, r3, bB + (uint32_t)ntp * 16u * LDA + koff);
                bf[ntp * 2][0] = r0; bf[ntp * 2][1] = r1;
                bf[ntp * 2 + 1][0] = r2; bf[ntp * 2 + 1][1] = r3;
            }

            #pragma unroll
            for (int mt = 0; mt < 4; ++mt)
                #pragma unroll
                for (int nt = 0; nt < 4; ++nt)
                    mma_f16(acc[mt][nt], af[mt][0], af[mt][1], af[mt][2], af[mt][3],
                            bf[nt][0], bf[nt][1]);
        }
    }

    const int g  = lane >> 2;
    const int tg = lane & 3;
    #pragma unroll
    for (int mt = 0; mt < 4; ++mt)
        #pragma unroll
        for (int nt = 0; nt < 4; ++nt) {
            int n    = wn * 32 + nt * 8 + tg * 2;
            int gsel = n >> 6;
            int c64  = n & 63;
            int e    = grp0 + gsel;           // 0..15 (V head index)
            const float* bp = bias + (size_t)e * 64;
            float b0 = bp[c64], b1 = bp[c64 + 1];
            int r0 = m0 + wm * 64 + mt * 16 + g;
            size_t base0 = ((size_t)e * 8192 + r0) * 64 + c64;
            size_t base1 = base0 + 8 * 64;
            *(uint32_t*)&g_v16[base0] =
                pack_f16x2(acc[mt][nt][0] + b0, acc[mt][nt][1] + b1);
            *(uint32_t*)&g_v16[base1] =
                pack_f16x2(acc[mt][nt][2] + b0, acc[mt][nt][3] + b1);
        }
}

// ============================================================================
// gemm_proj: 2-term split-fp16 GEMM (A = avhi+avlo fp16, B = Wp fp16).
//   out[row][n] = sum_k av[row][k]*Wp[n][k] + bp[n]. 2 MMAs per tile.
// ============================================================================
#define GP_AHI 0u
#define GP_ALO 10240u
#define GP_B   20480u
#define GP_STG 30720u
#define GP_SMEM (3 * 30720)

__global__ __launch_bounds__(256)
void gemm_proj(const float* __restrict__ bias, float* __restrict__ C)
{
    extern __shared__ __align__(128) char smem[];
    const uint32_t sb  = smem_u32(smem);
    const int tid  = threadIdx.x;
    const int lane = tid & 31;
    const int wid  = tid >> 5;
    const int wm   = wid & 1;
    const int wn   = wid >> 1;
    const int m0   = blockIdx.x * 128;
    const int n0   = blockIdx.y * 128;

    const __half* Ahi = g_avhi;
    const __half* Alo = g_avlo;
    const __half* B0  = g_wp16 + (size_t)n0 * 1024;

    float acc[4][4][4];
    #pragma unroll
    for (int mt = 0; mt < 4; ++mt)
        #pragma unroll
        for (int nt = 0; nt < 4; ++nt)
            #pragma unroll
            for (int i = 0; i < 4; ++i) acc[mt][nt][i] = 0.f;

    const int cp_r = tid >> 2;
    const int cp_c = tid & 3;
    const int ce   = cp_c * 8;
    auto issue = [&](int ks, uint32_t stg) {
        const int k0 = ks * 32;
        uint32_t d0 = stg + (uint32_t)cp_r * LDA + (uint32_t)cp_c * 16u;
        uint32_t d1 = d0 + 64u * LDA;
        size_t a0 = (size_t)(m0 + cp_r) * 1024 + k0 + ce;
        size_t a1 = a0 + 64 * 1024;
        size_t b0 = (size_t)cp_r * 1024 + k0 + ce;
        cp_async16(d0 + GP_AHI, Ahi + a0);
        cp_async16(d1 + GP_AHI, Ahi + a1);
        cp_async16(d0 + GP_ALO, Alo + a0);
        cp_async16(d1 + GP_ALO, Alo + a1);
        cp_async16(d0 + GP_B, B0 + b0);
        cp_async16(d1 + GP_B, B0 + 65536 + b0);
        cp_commit();
    };

    const uint32_t a_row = (uint32_t)(wm * 64 + (lane & 7) + ((lane >> 3) & 1) * 8);
    const uint32_t a_kb  = (uint32_t)(lane >> 4) * 16u;
    const uint32_t b_row = (uint32_t)(wn * 32 + (lane & 7) + (lane >> 4) * 8);
    const uint32_t b_kb  = (uint32_t)((lane >> 3) & 1) * 16u;

    issue(0, sb);
    issue(1, sb + GP_STG);

    for (int ks = 0; ks < 32; ++ks) {
        if (ks < 31) cp_wait<1>(); else cp_wait<0>();
        __syncthreads();
        if (ks + 2 < 32) issue(ks + 2, sb + (uint32_t)((ks + 2) % 3) * GP_STG);

        const uint32_t stg = sb + (uint32_t)(ks % 3) * GP_STG;
        const uint32_t aHi = stg + GP_AHI + a_row * LDA + a_kb;
        const uint32_t aLo = stg + GP_ALO + a_row * LDA + a_kb;
        const uint32_t bB  = stg + GP_B   + b_row * LDA + b_kb;

        #pragma unroll
        for (int kk = 0; kk < 2; ++kk) {
            const uint32_t koff = (uint32_t)kk * 32u;

            uint32_t ahi[4][4], alo[4][4];
            #pragma unroll
            for (int mt = 0; mt < 4; ++mt) {
                ldmatrix_x4(ahi[mt][0], ahi[mt][1], ahi[mt][2], ahi[mt][3],
                            aHi + (uint32_t)mt * 16u * LDA + koff);
                ldmatrix_x4(alo[mt][0], alo[mt][1], alo[mt][2], alo[mt][3],
                            aLo + (uint32_t)mt * 16u * LDA + koff);
            }
            uint32_t bf[4][2];
            #pragma unroll
            for (int ntp = 0; ntp < 2; ++ntp) {
                uint32_t r0, r1, r2, r3;
                ldmatrix_x4(r0, r1, r2, r3, bB + (uint32_t)ntp * 16u * LDA + koff);
                bf[ntp * 2][0] = r0; bf[ntp * 2][1] = r1;
                bf[ntp * 2 + 1][0] = r2; bf[ntp * 2 + 1][1] = r3;
            }

            #pragma unroll
            for (int mt = 0; mt < 4; ++mt)
                #pragma unroll
                for (int nt = 0; nt < 4; ++nt) {
                    mma_f16(acc[mt][nt], ahi[mt][0], ahi[mt][1], ahi[mt][2], ahi[mt][3],
                            bf[nt][0], bf[nt][1]);
                    mma_f16(acc[mt][nt], alo[mt][0], alo[mt][1], alo[mt][2], alo[mt][3],
                            bf[nt][0], bf[nt][1]);
                }
        }
    }

    const int g  = lane >> 2;
    const int tg = lane & 3;
    #pragma unroll
    for (int mt = 0; mt < 4; ++mt)
        #pragma unroll
        for (int nt = 0; nt < 4; ++nt) {
            int n = n0 + wn * 32 + nt * 8 + tg * 2;
            float b0 = bias[n], b1 = bias[n + 1];
            int r0 = m0 + wm * 64 + mt * 16 + g;
            float2 o0 = make_float2(acc[mt][nt][0] + b0, acc[mt][nt][1] + b1);
            float2 o1 = make_float2(acc[mt][nt][2] + b0, acc[mt][nt][3] + b1);
            *(float2*)(C + (size_t)r0 * 1024 + n)       = o0;
            *(float2*)(C + (size_t)(r0 + 8) * 1024 + n) = o1;
        }
}

// ============================================================================
// attn_mma: flash attention. Operands all pre-split/pre-converted:
//   Q/K bf16 hi/lo (Q pre-scaled), V fp16 transposed. S 3-term, PV 1-term.
//   3-stage cp.async, 2 CTAs/SM. Epilogue writes av split fp16.
// ============================================================================
#define LDS_ROW 144u
#define ST_KHI 0u
#define ST_KLO 9216u
#define ST_V16 18432u
#define STAGE_BYTES 27648u
#define ATTN_SMEM (3 * 27648)

__global__ __launch_bounds__(256, 2)
void attn_mma()
{
    extern __shared__ __align__(128) char smem[];
    const uint32_t sb = smem_u32(smem);
    const int tid  = threadIdx.x;
    const int lane = tid & 31;
    const int wid  = tid >> 5;
    const int g    = lane >> 2;
    const int tg   = lane & 3;
    const int hb   = blockIdx.y;
    const int hd   = hb >> 2;
    const int b    = hb & 3;
    const int q0   = blockIdx.x * 128;

    const __nv_bfloat16* Qhi = g_qhi + ((size_t)hd * 8192 + b * 2048 + q0) * 64;
    const __nv_bfloat16* Qlo = g_qlo + ((size_t)hd * 8192 + b * 2048 + q0) * 64;
    const __nv_bfloat16* Khi = g_khi + (size_t)hb * 2048 * 64;
    const __nv_bfloat16* Klo = g_klo + (size_t)hb * 2048 * 64;
    const __half*        V16 = g_vt16 + (size_t)hb * 64 * 2048;

    // ---- stage Q (pre-scaled, pre-split) via cp.async, extract fragments ----
    #pragma unroll
    for (int i = 0; i < 4; ++i) {
        int idx = tid + i * 256;           // < 1024: 128 rows x 8 granules of 16B
        int row = idx >> 3;
        int c   = idx & 7;
        cp_async16(sb + (uint32_t)row * LDS_ROW + (uint32_t)c * 16u,
                   Qhi + (size_t)row * 64 + c * 8);
        cp_async16(sb + 18432u + (uint32_t)row * LDS_ROW + (uint32_t)c * 16u,
                   Qlo + (size_t)row * 64 + c * 8);
    }
    cp_commit();
    cp_wait<0>();
    __syncthreads();

    uint32_t qhi[4][4], qlo[4][4];
    {
        const uint32_t qrow = (uint32_t)(wid * 16 + (lane & 7) + ((lane >> 3) & 1) * 8);
        const uint32_t kb   = (uint32_t)(lane >> 4) * 16u;
        const uint32_t aH = sb + qrow * LDS_ROW + kb;
        const uint32_t aL = sb + 18432u + qrow * LDS_ROW + kb;
        #pragma unroll
        for (int t = 0; t < 4; ++t) {
            ldmatrix_x4(qhi[t][0], qhi[t][1], qhi[t][2], qhi[t][3], aH + t * 32u);
            ldmatrix_x4(qlo[t][0], qlo[t][1], qlo[t][2], qlo[t][3], aL + t * 32u);
        }
    }
    __syncthreads();   // Q consumed — smem free for stages

    float mA = -1e30f, mB = -1e30f, lA = 0.f, lB = 0.f;
    float oacc[8][4];
    #pragma unroll
    for (int j = 0; j < 8; ++j)
        #pragma unroll
        for (int i = 0; i < 4; ++i) oacc[j][i] = 0.f;

    const uint32_t brow = (uint32_t)((lane & 7) + (lane >> 4) * 8);
    const uint32_t bkb  = (uint32_t)((lane >> 3) & 1) * 16u;

    const int cp_row = tid >> 3;     // 0..31
    const int cp_c   = tid & 7;      // 16B granule
    auto issue = [&](int j0, uint32_t stg) {
        #pragma unroll
        for (int i = 0; i < 2; ++i) {
            int row = cp_row + i * 32;
            uint32_t doff = stg + (uint32_t)row * LDS_ROW + (uint32_t)cp_c * 16u;
            cp_async16(doff + ST_KHI, Khi + ((size_t)(j0 + row)) * 64 + cp_c * 8);
            cp_async16(doff + ST_KLO, Klo + ((size_t)(j0 + row)) * 64 + cp_c * 8);
            cp_async16(doff + ST_V16, V16 + ((size_t)row) * 2048 + j0 + cp_c * 8);
        }
        cp_commit();
    };

    issue(0, sb);
    issue(64, sb + STAGE_BYTES);

    for (int j = 0; j < 32; ++j) {
        if (j < 31) cp_wait<1>(); else cp_wait<0>();
        __syncthreads();
        if (j + 2 < 32) issue((j + 2) * 64, sb + (uint32_t)((j + 2) % 3) * STAGE_BYTES);

        const uint32_t stg = sb + (uint32_t)(j % 3) * STAGE_BYTES;

        // ---- S = Qscaled @ K^T (split 3-term bf16), log2 units ----
        float sacc[8][4];
        #pragma unroll
        for (int jj = 0; jj < 8; ++jj)
            #pragma unroll
            for (int i = 0; i < 4; ++i) sacc[jj][i] = 0.f;

        #pragma unroll
        for (int td = 0; td < 4; ++td) {
            uint32_t bhi[8][2], blo[8][2];
            #pragma unroll
            for (int ntp = 0; ntp < 4; ++ntp) {
                uint32_t base = (uint32_t)(ntp * 16) * LDS_ROW + brow * LDS_ROW + bkb
                                + (uint32_t)td * 32u;
                uint32_t r0, r1, r2, r3;
                ldmatrix_x4(r0, r1, r2, r3, stg + ST_KHI + base);
                bhi[ntp * 2][0] = r0; bhi[ntp * 2][1] = r1;
                bhi[ntp * 2 + 1][0] = r2; bhi[ntp * 2 + 1][1] = r3;
                ldmatrix_x4(r0, r1, r2, r3, stg + ST_KLO + base);
                blo[ntp * 2][0] = r0; blo[ntp * 2][1] = r1;
                blo[ntp * 2 + 1][0] = r2; blo[ntp * 2 + 1][1] = r3;
            }
            #pragma unroll
            for (int nt = 0; nt < 8; ++nt) {
                mma_bf16(sacc[nt], qhi[td][0], qhi[td][1], qhi[td][2], qhi[td][3],
                         bhi[nt][0], bhi[nt][1]);
                mma_bf16(sacc[nt], qhi[td][0], qhi[td][1], qhi[td][2], qhi[td][3],
                         blo[nt][0], blo[nt][1]);
                mma_bf16(sacc[nt], qlo[td][0], qlo[td][1], qlo[td][2], qlo[td][3],
                         bhi[nt][0], bhi[nt][1]);
            }
        }

        // ---- online softmax (log2 domain) ----
        float rmA = -1e30f, rmB = -1e30f;
        #pragma unroll
        for (int jj = 0; jj < 8; ++jj) {
            rmA = fmaxf(rmA, fmaxf(sacc[jj][0], sacc[jj][1]));
            rmB = fmaxf(rmB, fmaxf(sacc[jj][2], sacc[jj][3]));
        }
        rmA = fmaxf(rmA, __shfl_xor_sync(0xffffffffu, rmA, 1));
        rmA = fmaxf(rmA, __shfl_xor_sync(0xffffffffu, rmA, 2));
        rmB = fmaxf(rmB, __shfl_xor_sync(0xffffffffu, rmB, 1));
        rmB = fmaxf(rmB, __shfl_xor_sync(0xffffffffu, rmB, 2));

        float mnA = fmaxf(mA, rmA), mnB = fmaxf(mB, rmB);
        float corrA = exp2_fast(mA - mnA), corrB = exp2_fast(mB - mnB);

        float sumA = 0.f, sumB = 0.f;
        uint32_t pf[4][4];        // P fragments, fp16
        #pragma unroll
        for (int jj = 0; jj < 8; ++jj) {
            float p0 = exp2_fast(sacc[jj][0] - mnA);
            float p1 = exp2_fast(sacc[jj][1] - mnA);
            float p2 = exp2_fast(sacc[jj][2] - mnB);
            float p3 = exp2_fast(sacc[jj][3] - mnB);
            sumA += p0 + p1; sumB += p2 + p3;
            int t = jj >> 1;
            int o = (jj & 1) * 2;
            pf[t][o]     = pack_f16x2(p0, p1);
            pf[t][o + 1] = pack_f16x2(p2, p3);
        }
        sumA += __shfl_xor_sync(0xffffffffu, sumA, 1);
        sumA += __shfl_xor_sync(0xffffffffu, sumA, 2);
        sumB += __shfl_xor_sync(0xffffffffu, sumB, 1);
        sumB += __shfl_xor_sync(0xffffffffu, sumB, 2);

        lA = lA * corrA + sumA;
        lB = lB * corrB + sumB;
        mA = mnA; mB = mnB;

        #pragma unroll
        for (int jj = 0; jj < 8; ++jj) {
            oacc[jj][0] *= corrA; oacc[jj][1] *= corrA;
            oacc[jj][2] *= corrB; oacc[jj][3] *= corrB;
        }

        // ---- O += P @ V (1-term fp16) ----
        #pragma unroll
        for (int t = 0; t < 4; ++t) {
            uint32_t vf[8][2];
            #pragma unroll
            for (int ntp = 0; ntp < 4; ++ntp) {
                uint32_t base = (uint32_t)(ntp * 16) * LDS_ROW + brow * LDS_ROW + bkb
                                + (uint32_t)t * 32u;
                uint32_t r0, r1, r2, r3;
                ldmatrix_x4(r0, r1, r2, r3, stg + ST_V16 + base);
                vf[ntp * 2][0] = r0; vf[ntp * 2][1] = r1;
                vf[ntp * 2 + 1][0] = r2; vf[ntp * 2 + 1][1] = r3;
            }
            #pragma unroll
            for (int nd = 0; nd < 8; ++nd)
                mma_f16(oacc[nd], pf[t][0], pf[t][1], pf[t][2], pf[t][3],
                        vf[nd][0], vf[nd][1]);
        }
    }

    // ---- epilogue: normalize, split to fp16 hi/lo, write g_avhi/g_avlo ----
    const float invA = 1.f / lA, invB = 1.f / lB;
    const int rowA = q0 + wid * 16 + g;
    const int rowB = rowA + 8;
    #pragma unroll
    for (int jd = 0; jd < 8; ++jd) {
        int col = hd * 64 + jd * 8 + tg * 2;
        {
            uint32_t h, l;
            split2_f16(oacc[jd][0] * invA, oacc[jd][1] * invA, h, l);
            size_t base = (size_t)(b * 2048 + rowA) * 1024 + col;
            *(uint32_t*)&g_avhi[base] = h;
            *(uint32_t*)&g_avlo[base] = l;
        }
        {
            uint32_t h, l;
            split2_f16(oacc[jd][2] * invB, oacc[jd][3] * invB, h, l);
            size_t base = (size_t)(b * 2048 + rowB) * 1024 + col;
            *(uint32_t*)&g_avhi[base] = h;
            *(uint32_t*)&g_avlo[base] = l;
        }
    }
}

// ============================================================================
extern "C" void kernel_launch(void* const* d_in, const int* in_sizes, int n_in,
                              void* d_out, int out_size)
{
    const float* x    = (const float*)d_in[0];   // (4, 2048, 1024)
    const float* Wqkv = (const float*)d_in[1];   // (48, 1024, 64)
    const float* bqkv = (const float*)d_in[2];   // (48, 64)
    const float* Wp   = (const float*)d_in[3];   // (1024, 1024)
    const float* bp   = (const float*)d_in[4];   // (1024,)
    float* out = (float*)d_out;                  // (4, 2048, 1024)

    cudaFuncSetAttribute(gemm_qk, cudaFuncAttributeMaxDynamicSharedMemorySize,
                         GEMM_SMEM);
    cudaFuncSetAttribute(gemm_v16, cudaFuncAttributeMaxDynamicSharedMemorySize,
                         GF_SMEM);
    cudaFuncSetAttribute(gemm_proj, cudaFuncAttributeMaxDynamicSharedMemorySize,
                         GP_SMEM);
    cudaFuncSetAttribute(attn_mma, cudaFuncAttributeMaxDynamicSharedMemorySize,
                         ATTN_SMEM);

    // 1) preps: split x (bf16 hi/lo + fp16), Wp -> fp16, transpose/split Wqkv
    prep_x<<<2048, 256>>>(x);
    prep_wp16<<<256, 256>>>(Wp);
    transpose_w<<<dim3(32, 2, 48), dim3(32, 8)>>>(Wqkv);

    // 2a) Q/K ensembles: 3-term bf16; epilogue emits pre-scaled/pre-split Q,K
    gemm_qk<<<dim3(64, 16), 256, GEMM_SMEM>>>(bqkv);
    // 2b) V ensembles: 1-term fp16 -> g_v16
    gemm_v16<<<dim3(64, 8), 256, GF_SMEM>>>(bqkv + 32 * 64);

    // 2.5) transpose V fp16 -> [hb][d][l]
    prep_vt<<<dim3(32, 64), 256>>>();

    // 3) attention (S bf16 3-term, PV fp16 1-term); emits av split fp16
    attn_mma<<<dim3(16, 64), 256, ATTN_SMEM>>>();

    // 4) proj: 2-term split-fp16  (out = av @ Wp^T + bp)
    gemm_proj<<<dim3(64, 8), 256, GP_SMEM>>>(bp, out);
}